// round 6
// baseline (speedup 1.0000x reference)
#include <cuda_runtime.h>
#include <cuda_bf16.h>
#include <cstdint>

#define NNODES 50000
#define NPAD   50048          // 391 * 128
#define NEDGES 1600000
#define CHID   128
#define KP     384            // split-bf16 K' = 3 * 128
#define KPAD   392            // smem row pitch in bf16 (16B aligned, conflict-free ldmatrix)

// ---------------- scratch (no allocations allowed) ----------------
__device__ float g_bufA[NNODES * CHID];
__device__ float g_bufB[NNODES * CHID];
__device__ float g_es[NNODES];
__device__ float g_ed[NNODES];
__device__ int   g_rowptr[NNODES + 1];
__device__ int   g_counts[NNODES];
__device__ int   g_cursor[NNODES];
__device__ int   g_srcs[NEDGES];
__device__ __nv_bfloat16 g_Abf[(size_t)NPAD * KP];   // padded rows stay zero (static zero-init)
__device__ __nv_bfloat16 g_Bbf[(size_t)CHID * KP];

__device__ __forceinline__ float lrelu(float x) { return x > 0.f ? x : 0.2f * x; }

__device__ __forceinline__ uint32_t smem_u32(const void* p) {
    uint32_t a;
    asm("{ .reg .u64 t; cvta.to.shared.u64 t, %1; cvt.u32.u64 %0, t; }" : "=r"(a) : "l"(p));
    return a;
}
__device__ __forceinline__ void ldm_x4(uint32_t* r, uint32_t addr) {
    asm volatile("ldmatrix.sync.aligned.m8n8.x4.shared.b16 {%0,%1,%2,%3}, [%4];"
                 : "=r"(r[0]), "=r"(r[1]), "=r"(r[2]), "=r"(r[3]) : "r"(addr));
}
__device__ __forceinline__ void mma16816(float* c, const uint32_t* a, const uint32_t* b) {
    asm volatile("mma.sync.aligned.m16n8k16.row.col.f32.bf16.bf16.f32 "
                 "{%0,%1,%2,%3}, {%4,%5,%6,%7}, {%8,%9}, {%0,%1,%2,%3};"
                 : "+f"(c[0]), "+f"(c[1]), "+f"(c[2]), "+f"(c[3])
                 : "r"(a[0]), "r"(a[1]), "r"(a[2]), "r"(a[3]), "r"(b[0]), "r"(b[1]));
}

// ---------------- CSR build ----------------
__global__ void zero_int_kernel(int* a, int n) {
    int i = blockIdx.x * blockDim.x + threadIdx.x;
    if (i < n) a[i] = 0;
}

__global__ void count_kernel(const int* __restrict__ dst, int* __restrict__ counts, int E) {
    for (int e = blockIdx.x * blockDim.x + threadIdx.x; e < E; e += gridDim.x * blockDim.x)
        atomicAdd(&counts[dst[e]], 1);
}

// 1024-thread two-pass scan: writes rowptr and cursor (= exclusive prefix)
__global__ void scan_kernel(const int* __restrict__ counts, int* __restrict__ rowptr,
                            int* __restrict__ cursor, int n) {
    __shared__ int warp_sums[32];
    int tid = threadIdx.x;
    int CH = (n + 1023) >> 10;
    int start = tid * CH;
    int end = min(start + CH, n);
    int s = 0;
    for (int i = start; i < end; i++) s += counts[i];
    int lane = tid & 31, wid = tid >> 5;
    int v = s;
#pragma unroll
    for (int o = 1; o < 32; o <<= 1) { int t = __shfl_up_sync(~0u, v, o); if (lane >= o) v += t; }
    if (lane == 31) warp_sums[wid] = v;
    __syncthreads();
    if (wid == 0) {
        int w = warp_sums[lane];
#pragma unroll
        for (int o = 1; o < 32; o <<= 1) { int t = __shfl_up_sync(~0u, w, o); if (lane >= o) w += t; }
        warp_sums[lane] = w;
    }
    __syncthreads();
    int excl = v - s + (wid > 0 ? warp_sums[wid - 1] : 0);
    int run = excl;
    for (int i = start; i < end; i++) {
        cursor[i] = run;
        run += counts[i];
        rowptr[i + 1] = run;
    }
    if (tid == 0) rowptr[0] = 0;
}

__global__ void scatter_kernel(const int* __restrict__ src, const int* __restrict__ dst,
                               int* __restrict__ cursor, int* __restrict__ out, int E) {
    for (int e = blockIdx.x * blockDim.x + threadIdx.x; e < E; e += gridDim.x * blockDim.x) {
        int d = dst[e];
        int pos = atomicAdd(&cursor[d], 1);
        out[pos] = src[e];
    }
}

// ---------------- split-bf16 conversion ----------------
// A'[row, 0:128)=hi(x), [128:256)=lo(x), [256:384)=hi(x)
__global__ void split_x_kernel(const float* __restrict__ in, __nv_bfloat16* __restrict__ out, int M) {
    int idx = blockIdx.x * blockDim.x + threadIdx.x;
    if (idx >= M * CHID) return;
    int row = idx >> 7, c = idx & 127;
    float vf = in[idx];
    __nv_bfloat16 hi = __float2bfloat16(vf);
    __nv_bfloat16 lo = __float2bfloat16(vf - __bfloat162float(hi));
    size_t base = (size_t)row * KP;
    out[base + c] = hi;
    out[base + 128 + c] = lo;
    out[base + 256 + c] = hi;
}

// B'[n, 0:128)=hi(W^T), [128:256)=hi(W^T), [256:384)=lo(W^T)   (W is [K=128, N] row-major)
__global__ void split_w_kernel(const float* __restrict__ W, __nv_bfloat16* __restrict__ out, int Ncol) {
    int idx = blockIdx.x * blockDim.x + threadIdx.x;
    if (idx >= 128 * Ncol) return;
    int k = idx / Ncol, n = idx % Ncol;
    float vf = W[idx];
    __nv_bfloat16 hi = __float2bfloat16(vf);
    __nv_bfloat16 lo = __float2bfloat16(vf - __bfloat162float(hi));
    size_t base = (size_t)n * KP;
    out[base + k] = hi;
    out[base + 128 + k] = hi;
    out[base + 256 + k] = lo;
}

// ---------------- mma.sync bf16 GEMM: out[M, BN] = A'[M, KP] @ B'[BN, KP]^T ----------------
// One 128-row tile per CTA; full K'=384 panels resident in smem. 8 warps = 4(M) x 2(N).
template <int BN>
__global__ __launch_bounds__(256, 1) void mma_gemm_kernel(
    const __nv_bfloat16* __restrict__ A, const __nv_bfloat16* __restrict__ B,
    float* __restrict__ out, int M) {
    extern __shared__ __align__(16) __nv_bfloat16 sm[];
    __nv_bfloat16* As = sm;                  // [128][KPAD]
    __nv_bfloat16* Bs = sm + 128 * KPAD;     // [BN][KPAD]
    const int tid = threadIdx.x, wid = tid >> 5, lane = tid & 31;
    const int tile = blockIdx.x;

    // load A tile (128 x 384 bf16) and B panel (BN x 384) as 16B chunks
    const uint4* Ag = reinterpret_cast<const uint4*>(A + (size_t)tile * 128 * KP);
    for (int idx = tid; idx < 128 * 48; idx += 256) {
        int row = idx / 48, ch = idx % 48;
        *reinterpret_cast<uint4*>(As + row * KPAD + ch * 8) = Ag[row * 48 + ch];
    }
    const uint4* Bg = reinterpret_cast<const uint4*>(B);
    for (int idx = tid; idx < BN * 48; idx += 256) {
        int row = idx / 48, ch = idx % 48;
        *reinterpret_cast<uint4*>(Bs + row * KPAD + ch * 8) = Bg[row * 48 + ch];
    }
    __syncthreads();

    constexpr int WN = BN / 2;      // warp N extent: 64 or 32
    constexpr int NT = WN / 8;      // n-tiles per warp: 8 or 4
    const int wm = wid & 3, wn = wid >> 2;
    const int m0 = wm * 32, n0 = wn * WN;

    float acc[2][NT][4];
#pragma unroll
    for (int i = 0; i < 2; i++)
#pragma unroll
        for (int j = 0; j < NT; j++)
#pragma unroll
            for (int q = 0; q < 4; q++) acc[i][j][q] = 0.f;

    const uint32_t as_base = smem_u32(As);
    const uint32_t bs_base = smem_u32(Bs);
    const int a_row = m0 + (lane & 15);
    const int a_koff = (lane >> 4) * 8;
    const int b_roff = (lane & 7) + ((lane >> 4) << 3);
    const int b_koff = ((lane >> 3) & 1) * 8;

    for (int ks = 0; ks < 24; ks++) {
        const int k0 = ks * 16;
        uint32_t a_regs[2][4];
#pragma unroll
        for (int mt = 0; mt < 2; mt++) {
            uint32_t addr = as_base + (uint32_t)(((a_row + mt * 16) * KPAD + k0 + a_koff) * 2);
            ldm_x4(a_regs[mt], addr);
        }
        uint32_t b_regs[NT][2];
#pragma unroll
        for (int np = 0; np < NT / 2; np++) {
            uint32_t addr = bs_base + (uint32_t)(((n0 + np * 16 + b_roff) * KPAD + k0 + b_koff) * 2);
            uint32_t r[4];
            ldm_x4(r, addr);
            b_regs[np * 2][0] = r[0]; b_regs[np * 2][1] = r[1];
            b_regs[np * 2 + 1][0] = r[2]; b_regs[np * 2 + 1][1] = r[3];
        }
#pragma unroll
        for (int mt = 0; mt < 2; mt++)
#pragma unroll
            for (int nt = 0; nt < NT; nt++)
                mma16816(acc[mt][nt], a_regs[mt], b_regs[nt]);
    }

    // epilogue
    const int g = lane >> 2, q = lane & 3;
#pragma unroll
    for (int mt = 0; mt < 2; mt++) {
        int r0 = tile * 128 + m0 + mt * 16 + g;
        int r1 = r0 + 8;
#pragma unroll
        for (int nt = 0; nt < NT; nt++) {
            int col = n0 + nt * 8 + q * 2;
            if (r0 < M)
                *reinterpret_cast<float2*>(out + (size_t)r0 * BN + col) =
                    make_float2(acc[mt][nt][0], acc[mt][nt][1]);
            if (r1 < M)
                *reinterpret_cast<float2*>(out + (size_t)r1 * BN + col) =
                    make_float2(acc[mt][nt][2], acc[mt][nt][3]);
        }
    }
}

// ---------------- attention scalar coefficients es/ed ----------------
__global__ void attn_kernel(const float* __restrict__ h, const float* __restrict__ asv,
                            const float* __restrict__ adv, float* __restrict__ es,
                            float* __restrict__ ed, int N, int C) {
    int gw = (blockIdx.x * blockDim.x + threadIdx.x) >> 5;
    int lane = threadIdx.x & 31;
    if (gw >= N) return;
    float s = 0.f, d = 0.f;
    for (int c = lane; c < C; c += 32) {
        float v = h[(size_t)gw * C + c];
        s += v * asv[c];
        d += v * adv[c];
    }
#pragma unroll
    for (int o = 16; o; o >>= 1) {
        s += __shfl_xor_sync(0xffffffffu, s, o);
        d += __shfl_xor_sync(0xffffffffu, d, o);
    }
    if (lane == 0) { es[gw] = s; ed[gw] = d; }
}

// ---------------- edge-softmax + aggregation: one block per dst node ----------------
__global__ void agg_kernel(const float* __restrict__ h, const float* __restrict__ es,
                           const float* __restrict__ ed, const int* __restrict__ rowptr,
                           const int* __restrict__ srcs, const float* __restrict__ bias,
                           float* __restrict__ out, int C, int do_relu) {
    int d = blockIdx.x;
    int tid = threadIdx.x;
    int start = rowptr[d], end = rowptr[d + 1];
    float edv = ed[d];
    float self_l = lrelu(es[d] + edv);

    float lmax = self_l;
    for (int e = start + tid; e < end; e += blockDim.x)
        lmax = fmaxf(lmax, lrelu(es[srcs[e]] + edv));
#pragma unroll
    for (int o = 16; o; o >>= 1)
        lmax = fmaxf(lmax, __shfl_xor_sync(0xffffffffu, lmax, o));
    __shared__ float red[4];
    if ((tid & 31) == 0) red[tid >> 5] = lmax;
    __syncthreads();
    if (tid == 0) {
        float m0 = red[0];
        int nw = blockDim.x >> 5;
        for (int w = 1; w < nw; w++) m0 = fmaxf(m0, red[w]);
        red[0] = m0;
    }
    __syncthreads();
    float m = red[0];

    __shared__ float w_sh[128];
    __shared__ int   s_sh[128];
    float wself = __expf(self_l - m);
    float acc = wself * h[(size_t)d * C + tid];
    float denom = wself;
    for (int base = start; base < end; base += blockDim.x) {
        int e = base + tid;
        if (e < end) {
            int s = srcs[e];
            s_sh[tid] = s;
            w_sh[tid] = __expf(lrelu(es[s] + edv) - m);
        }
        __syncthreads();
        int cnt = min((int)blockDim.x, end - base);
        for (int j = 0; j < cnt; j++) {
            float w = w_sh[j];
            acc += w * h[(size_t)s_sh[j] * C + tid];
            denom += w;
        }
        __syncthreads();
    }
    float o = acc / denom + bias[tid];
    if (do_relu) o = fmaxf(o, 0.f);
    out[(size_t)d * C + tid] = o;
}

// ---------------- launch ----------------
extern "C" void kernel_launch(void* const* d_in, const int* in_sizes, int n_in,
                              void* d_out, int out_size) {
    const float* x   = (const float*)d_in[0];
    const int*   ei  = (const int*)  d_in[1];
    const float* W0  = (const float*)d_in[2];
    const float* as0 = (const float*)d_in[3];
    const float* ad0 = (const float*)d_in[4];
    const float* b0  = (const float*)d_in[5];
    const float* W1  = (const float*)d_in[6];
    const float* as1 = (const float*)d_in[7];
    const float* ad1 = (const float*)d_in[8];
    const float* b1  = (const float*)d_in[9];
    const float* W2  = (const float*)d_in[10];
    const float* as2 = (const float*)d_in[11];
    const float* ad2 = (const float*)d_in[12];
    const float* b2  = (const float*)d_in[13];
    float* out = (float*)d_out;

    const int N = in_sizes[0] / CHID;   // 50000
    const int E = in_sizes[1] / 2;      // 1600000
    const int* srcp = ei;
    const int* dstp = ei + E;

    float *bufA, *bufB, *es, *ed;
    int *rowptr, *counts, *cursor, *srcs;
    __nv_bfloat16 *Abf, *Bbf;
    cudaGetSymbolAddress((void**)&bufA,   g_bufA);
    cudaGetSymbolAddress((void**)&bufB,   g_bufB);
    cudaGetSymbolAddress((void**)&es,     g_es);
    cudaGetSymbolAddress((void**)&ed,     g_ed);
    cudaGetSymbolAddress((void**)&rowptr, g_rowptr);
    cudaGetSymbolAddress((void**)&counts, g_counts);
    cudaGetSymbolAddress((void**)&cursor, g_cursor);
    cudaGetSymbolAddress((void**)&srcs,   g_srcs);
    cudaGetSymbolAddress((void**)&Abf,    g_Abf);
    cudaGetSymbolAddress((void**)&Bbf,    g_Bbf);

    const int smem128 = (128 + 128) * KPAD * 2;   // 200704
    const int smem64  = (128 + 64)  * KPAD * 2;   // 150528
    static bool attr_set = false;
    if (!attr_set) {
        cudaFuncSetAttribute(mma_gemm_kernel<128>, cudaFuncAttributeMaxDynamicSharedMemorySize, smem128);
        cudaFuncSetAttribute(mma_gemm_kernel<64>,  cudaFuncAttributeMaxDynamicSharedMemorySize, smem64);
        attr_set = true;
    }

    // CSR by destination (same for all 3 layers)
    zero_int_kernel<<<(N + 255) / 256, 256>>>(counts, N);
    count_kernel<<<592, 256>>>(dstp, counts, E);
    scan_kernel<<<1, 1024>>>(counts, rowptr, cursor, N);
    scatter_kernel<<<592, 256>>>(srcp, dstp, cursor, srcs, E);

    const int tiles = (N + 127) / 128;   // 391
    int attn_blocks = (N + 7) / 8;
    int splitx_blocks = (N * CHID + 255) / 256;

    // layer 0
    split_x_kernel<<<splitx_blocks, 256>>>(x, Abf, N);
    split_w_kernel<<<(128 * 128 + 255) / 256, 256>>>(W0, Bbf, 128);
    mma_gemm_kernel<128><<<tiles, 256, smem128>>>(Abf, Bbf, bufA, N);
    attn_kernel<<<attn_blocks, 256>>>(bufA, as0, ad0, es, ed, N, 128);
    agg_kernel<<<N, 128>>>(bufA, es, ed, rowptr, srcs, b0, bufB, 128, 1);

    // layer 1
    split_x_kernel<<<splitx_blocks, 256>>>(bufB, Abf, N);
    split_w_kernel<<<(128 * 128 + 255) / 256, 256>>>(W1, Bbf, 128);
    mma_gemm_kernel<128><<<tiles, 256, smem128>>>(Abf, Bbf, bufA, N);
    attn_kernel<<<attn_blocks, 256>>>(bufA, as1, ad1, es, ed, N, 128);
    agg_kernel<<<N, 128>>>(bufA, es, ed, rowptr, srcs, b1, bufB, 128, 1);

    // layer 2 (C_out = 64)
    split_x_kernel<<<splitx_blocks, 256>>>(bufB, Abf, N);
    split_w_kernel<<<(128 * 64 + 255) / 256, 256>>>(W2, Bbf, 64);
    mma_gemm_kernel<64><<<tiles, 256, smem64>>>(Abf, Bbf, bufA, N);
    attn_kernel<<<attn_blocks, 256>>>(bufA, as2, ad2, es, ed, N, 64);
    agg_kernel<<<N, 64>>>(bufA, es, ed, rowptr, srcs, b2, out, 64, 0);
}

// round 7
// speedup vs baseline: 1.2003x; 1.2003x over previous
#include <cuda_runtime.h>
#include <cuda_bf16.h>
#include <cstdint>

#define NNODES 50000
#define NPAD   50048          // 391 * 128
#define NEDGES 1600000
#define CHID   128
#define KP     384            // split-bf16 K' = 3 * 128
#define KPAD   392            // smem row pitch in bf16

// ---------------- scratch (no allocations allowed) ----------------
__device__ float g_bufA[NNODES * CHID];
__device__ float g_es[NNODES];
__device__ float g_ed[NNODES];
__device__ int   g_rowptr[NNODES + 1];
__device__ int   g_counts[NNODES];
__device__ int   g_cursor[NNODES];
__device__ int   g_srcs[NEDGES];
__device__ __nv_bfloat16 g_Abf[(size_t)NPAD * KP];   // padded rows stay zero
__device__ __nv_bfloat16 g_Bbf[(size_t)CHID * KP];

__device__ __forceinline__ float lrelu(float x) { return x > 0.f ? x : 0.2f * x; }

__device__ __forceinline__ uint32_t smem_u32(const void* p) {
    uint32_t a;
    asm("{ .reg .u64 t; cvta.to.shared.u64 t, %1; cvt.u32.u64 %0, t; }" : "=r"(a) : "l"(p));
    return a;
}
__device__ __forceinline__ void ldm_x4(uint32_t* r, uint32_t addr) {
    asm volatile("ldmatrix.sync.aligned.m8n8.x4.shared.b16 {%0,%1,%2,%3}, [%4];"
                 : "=r"(r[0]), "=r"(r[1]), "=r"(r[2]), "=r"(r[3]) : "r"(addr));
}
__device__ __forceinline__ void mma16816(float* c, const uint32_t* a, const uint32_t* b) {
    asm volatile("mma.sync.aligned.m16n8k16.row.col.f32.bf16.bf16.f32 "
                 "{%0,%1,%2,%3}, {%4,%5,%6,%7}, {%8,%9}, {%0,%1,%2,%3};"
                 : "+f"(c[0]), "+f"(c[1]), "+f"(c[2]), "+f"(c[3])
                 : "r"(a[0]), "r"(a[1]), "r"(a[2]), "r"(a[3]), "r"(b[0]), "r"(b[1]));
}

// ---------------- CSR build ----------------
__global__ void zero_int_kernel(int* a, int n) {
    int i = blockIdx.x * blockDim.x + threadIdx.x;
    if (i < n) a[i] = 0;
}

__global__ void count_kernel(const int* __restrict__ dst, int* __restrict__ counts, int E) {
    int e = blockIdx.x * blockDim.x + threadIdx.x;
    if (e < E) atomicAdd(&counts[dst[e]], 1);
}

__global__ void scan_kernel(const int* __restrict__ counts, int* __restrict__ rowptr,
                            int* __restrict__ cursor, int n) {
    __shared__ int warp_sums[32];
    int tid = threadIdx.x;
    int CH = (n + 1023) >> 10;
    int start = tid * CH;
    int end = min(start + CH, n);
    int s = 0;
    for (int i = start; i < end; i++) s += counts[i];
    int lane = tid & 31, wid = tid >> 5;
    int v = s;
#pragma unroll
    for (int o = 1; o < 32; o <<= 1) { int t = __shfl_up_sync(~0u, v, o); if (lane >= o) v += t; }
    if (lane == 31) warp_sums[wid] = v;
    __syncthreads();
    if (wid == 0) {
        int w = warp_sums[lane];
#pragma unroll
        for (int o = 1; o < 32; o <<= 1) { int t = __shfl_up_sync(~0u, w, o); if (lane >= o) w += t; }
        warp_sums[lane] = w;
    }
    __syncthreads();
    int excl = v - s + (wid > 0 ? warp_sums[wid - 1] : 0);
    int run = excl;
    for (int i = start; i < end; i++) {
        cursor[i] = run;
        run += counts[i];
        rowptr[i + 1] = run;
    }
    if (tid == 0) rowptr[0] = 0;
}

__global__ void scatter_kernel(const int* __restrict__ src, const int* __restrict__ dst,
                               int* __restrict__ cursor, int* __restrict__ out, int E) {
    int e = blockIdx.x * blockDim.x + threadIdx.x;
    if (e < E) {
        int d = dst[e];
        int pos = atomicAdd(&cursor[d], 1);
        out[pos] = src[e];
    }
}

// ---------------- split-bf16 conversion (layer 0 input only) ----------------
__global__ void split_x_kernel(const float* __restrict__ in, __nv_bfloat16* __restrict__ out, int M) {
    int idx = blockIdx.x * blockDim.x + threadIdx.x;
    if (idx >= M * CHID) return;
    int row = idx >> 7, c = idx & 127;
    float vf = in[idx];
    __nv_bfloat16 hi = __float2bfloat16(vf);
    __nv_bfloat16 lo = __float2bfloat16(vf - __bfloat162float(hi));
    size_t base = (size_t)row * KP;
    out[base + c] = hi;
    out[base + 128 + c] = lo;
    out[base + 256 + c] = hi;
}

// W is [K=128, N] row-major; B'[n] = [hi(W^T), hi(W^T), lo(W^T)]
__global__ void split_w_kernel(const float* __restrict__ W, __nv_bfloat16* __restrict__ out, int Ncol) {
    int idx = blockIdx.x * blockDim.x + threadIdx.x;
    if (idx >= 128 * Ncol) return;
    int k = idx / Ncol, n = idx % Ncol;
    float vf = W[idx];
    __nv_bfloat16 hi = __float2bfloat16(vf);
    __nv_bfloat16 lo = __float2bfloat16(vf - __bfloat162float(hi));
    size_t base = (size_t)n * KP;
    out[base + k] = hi;
    out[base + 128 + k] = hi;
    out[base + 256 + k] = lo;
}

// ---------------- mma.sync bf16 GEMM: out[M, BN] = A'[M, KP] @ B'[BN, KP]^T ----------------
// One 128-row tile per CTA; full K'=384 panels resident in smem; 2-stage register pipeline.
template <int BN>
__global__ __launch_bounds__(256, 1) void mma_gemm_kernel(
    const __nv_bfloat16* __restrict__ A, const __nv_bfloat16* __restrict__ B,
    float* __restrict__ out, int M) {
    extern __shared__ __align__(16) __nv_bfloat16 sm[];
    __nv_bfloat16* As = sm;                  // [128][KPAD]
    __nv_bfloat16* Bs = sm + 128 * KPAD;     // [BN][KPAD]
    const int tid = threadIdx.x, wid = tid >> 5, lane = tid & 31;
    const int tile = blockIdx.x;

    const uint4* Ag = reinterpret_cast<const uint4*>(A + (size_t)tile * 128 * KP);
    for (int idx = tid; idx < 128 * 48; idx += 256) {
        int row = idx / 48, ch = idx % 48;
        *reinterpret_cast<uint4*>(As + row * KPAD + ch * 8) = Ag[row * 48 + ch];
    }
    const uint4* Bg = reinterpret_cast<const uint4*>(B);
    for (int idx = tid; idx < BN * 48; idx += 256) {
        int row = idx / 48, ch = idx % 48;
        *reinterpret_cast<uint4*>(Bs + row * KPAD + ch * 8) = Bg[row * 48 + ch];
    }
    __syncthreads();

    constexpr int WN = BN / 2;
    constexpr int NT = WN / 8;
    const int wm = wid & 3, wn = wid >> 2;
    const int m0 = wm * 32, n0 = wn * WN;

    float acc[2][NT][4];
#pragma unroll
    for (int i = 0; i < 2; i++)
#pragma unroll
        for (int j = 0; j < NT; j++)
#pragma unroll
            for (int q = 0; q < 4; q++) acc[i][j][q] = 0.f;

    const uint32_t as_base = smem_u32(As);
    const uint32_t bs_base = smem_u32(Bs);
    const int a_row = m0 + (lane & 15);
    const int a_koff = (lane >> 4) * 8;
    const int b_roff = (lane & 7) + ((lane >> 4) << 3);
    const int b_koff = ((lane >> 3) & 1) * 8;

    uint32_t a_regs[2][2][4];
    uint32_t b_regs[2][NT][2];

#define LOAD_K(ks, buf) do {                                                              \
        const int _k0 = (ks) * 16;                                                        \
        _Pragma("unroll")                                                                 \
        for (int mt = 0; mt < 2; mt++) {                                                  \
            uint32_t addr = as_base + (uint32_t)(((a_row + mt * 16) * KPAD + _k0 + a_koff) * 2); \
            ldm_x4(a_regs[buf][mt], addr);                                                \
        }                                                                                 \
        _Pragma("unroll")                                                                 \
        for (int np = 0; np < NT / 2; np++) {                                             \
            uint32_t addr = bs_base + (uint32_t)(((n0 + np * 16 + b_roff) * KPAD + _k0 + b_koff) * 2); \
            uint32_t r[4];                                                                \
            ldm_x4(r, addr);                                                              \
            b_regs[buf][np * 2][0] = r[0];     b_regs[buf][np * 2][1] = r[1];             \
            b_regs[buf][np * 2 + 1][0] = r[2]; b_regs[buf][np * 2 + 1][1] = r[3];         \
        }                                                                                 \
    } while (0)

    LOAD_K(0, 0);
#pragma unroll
    for (int ks = 0; ks < 24; ks++) {
        const int cur = ks & 1;
        if (ks < 23) LOAD_K(ks + 1, cur ^ 1);
#pragma unroll
        for (int mt = 0; mt < 2; mt++)
#pragma unroll
            for (int nt = 0; nt < NT; nt++)
                mma16816(acc[mt][nt], a_regs[cur][mt], b_regs[cur][nt]);
    }
#undef LOAD_K

    const int g = lane >> 2, q = lane & 3;
#pragma unroll
    for (int mt = 0; mt < 2; mt++) {
        int r0 = tile * 128 + m0 + mt * 16 + g;
        int r1 = r0 + 8;
#pragma unroll
        for (int nt = 0; nt < NT; nt++) {
            int col = n0 + nt * 8 + q * 2;
            if (r0 < M)
                *reinterpret_cast<float2*>(out + (size_t)r0 * BN + col) =
                    make_float2(acc[mt][nt][0], acc[mt][nt][1]);
            if (r1 < M)
                *reinterpret_cast<float2*>(out + (size_t)r1 * BN + col) =
                    make_float2(acc[mt][nt][2], acc[mt][nt][3]);
        }
    }
}

// ---------------- attention scalar coefficients es/ed (warp per node, vectorized) ----------------
template <int C>
__global__ void attn_kernel(const float* __restrict__ h, const float* __restrict__ asv,
                            const float* __restrict__ adv, float* __restrict__ es,
                            float* __restrict__ ed, int N) {
    int gw = (blockIdx.x * blockDim.x + threadIdx.x) >> 5;
    int lane = threadIdx.x & 31;
    if (gw >= N) return;
    float s = 0.f, d = 0.f;
    if constexpr (C == 128) {
        float4 hv = *reinterpret_cast<const float4*>(h + (size_t)gw * C + lane * 4);
        float4 av = *reinterpret_cast<const float4*>(asv + lane * 4);
        float4 dv = *reinterpret_cast<const float4*>(adv + lane * 4);
        s = hv.x * av.x + hv.y * av.y + hv.z * av.z + hv.w * av.w;
        d = hv.x * dv.x + hv.y * dv.y + hv.z * dv.z + hv.w * dv.w;
    } else {
        float2 hv = *reinterpret_cast<const float2*>(h + (size_t)gw * C + lane * 2);
        float2 av = *reinterpret_cast<const float2*>(asv + lane * 2);
        float2 dv = *reinterpret_cast<const float2*>(adv + lane * 2);
        s = hv.x * av.x + hv.y * av.y;
        d = hv.x * dv.x + hv.y * dv.y;
    }
#pragma unroll
    for (int o = 16; o; o >>= 1) {
        s += __shfl_xor_sync(0xffffffffu, s, o);
        d += __shfl_xor_sync(0xffffffffu, d, o);
    }
    if (lane == 0) { es[gw] = s; ed[gw] = d; }
}

// ---------------- edge-softmax + aggregation ----------------
// One block (128 threads = 4 warps) per dst node. Warps partition EDGES; each warp
// gathers a full C-channel row per edge via vector loads (LDG.128 warp-wide).
// MODE 0: write fp32 out (no relu). MODE 1: write relu'd bf16 hi/lo/hi triple into Abf.
template <int C, int MODE>
__global__ __launch_bounds__(128) void agg_kernel(
    const float* __restrict__ h, const float* __restrict__ es,
    const float* __restrict__ ed, const int* __restrict__ rowptr,
    const int* __restrict__ srcs, const float* __restrict__ bias,
    float* __restrict__ out_f32, __nv_bfloat16* __restrict__ out_bf) {
    constexpr int V = C / 32;                 // floats per lane (4 or 2)
    const int d = blockIdx.x;
    const int tid = threadIdx.x, wid = tid >> 5, lane = tid & 31;
    const int start = rowptr[d], end = rowptr[d + 1];
    const float edv = ed[d];
    const float self_l = lrelu(es[d] + edv);

    // pass 1: segment max (tid-strided, coalesced over srcs)
    float lmax = self_l;
    for (int e = start + tid; e < end; e += 128)
        lmax = fmaxf(lmax, lrelu(es[srcs[e]] + edv));
#pragma unroll
    for (int o = 16; o; o >>= 1)
        lmax = fmaxf(lmax, __shfl_xor_sync(0xffffffffu, lmax, o));
    __shared__ float redm[4];
    if (lane == 0) redm[wid] = lmax;
    __syncthreads();
    const float m = fmaxf(fmaxf(redm[0], redm[1]), fmaxf(redm[2], redm[3]));

    // pass 2: warps partition edges; each warp gathers full rows
    float acc[V];
#pragma unroll
    for (int i = 0; i < V; i++) acc[i] = 0.f;
    float denom = 0.f;

    if (wid == 0) {   // implicit self loop
        float w = __expf(self_l - m);
        const float* hp = h + (size_t)d * C + lane * V;
#pragma unroll
        for (int i = 0; i < V; i++) acc[i] = w * hp[i];
        denom = w;
    }
    for (int e = start + wid; e < end; e += 4) {
        int s = srcs[e];
        float w = __expf(lrelu(es[s] + edv) - m);
        const float* hp = h + (size_t)s * C + lane * V;
        if constexpr (V == 4) {
            float4 hv = *reinterpret_cast<const float4*>(hp);
            acc[0] += w * hv.x; acc[1] += w * hv.y; acc[2] += w * hv.z; acc[3] += w * hv.w;
        } else {
            float2 hv = *reinterpret_cast<const float2*>(hp);
            acc[0] += w * hv.x; acc[1] += w * hv.y;
        }
        denom += w;
    }

    // cross-warp reduce
    __shared__ float red_acc[4 * C];
    __shared__ float red_den[4];
#pragma unroll
    for (int i = 0; i < V; i++) red_acc[wid * C + lane * V + i] = acc[i];
    if (lane == 0) red_den[wid] = denom;
    __syncthreads();

    if (tid < C) {
        float den = red_den[0] + red_den[1] + red_den[2] + red_den[3];
        float v = red_acc[tid] + red_acc[C + tid] + red_acc[2 * C + tid] + red_acc[3 * C + tid];
        float o = v / den + bias[tid];
        if constexpr (MODE == 1) {
            o = fmaxf(o, 0.f);
            __nv_bfloat16 hi = __float2bfloat16(o);
            __nv_bfloat16 lo = __float2bfloat16(o - __bfloat162float(hi));
            size_t base = (size_t)d * KP;
            out_bf[base + tid] = hi;
            out_bf[base + 128 + tid] = lo;
            out_bf[base + 256 + tid] = hi;
        } else {
            out_f32[(size_t)d * C + tid] = o;
        }
    }
}

// ---------------- launch ----------------
extern "C" void kernel_launch(void* const* d_in, const int* in_sizes, int n_in,
                              void* d_out, int out_size) {
    const float* x   = (const float*)d_in[0];
    const int*   ei  = (const int*)  d_in[1];
    const float* W0  = (const float*)d_in[2];
    const float* as0 = (const float*)d_in[3];
    const float* ad0 = (const float*)d_in[4];
    const float* b0  = (const float*)d_in[5];
    const float* W1  = (const float*)d_in[6];
    const float* as1 = (const float*)d_in[7];
    const float* ad1 = (const float*)d_in[8];
    const float* b1  = (const float*)d_in[9];
    const float* W2  = (const float*)d_in[10];
    const float* as2 = (const float*)d_in[11];
    const float* ad2 = (const float*)d_in[12];
    const float* b2  = (const float*)d_in[13];
    float* out = (float*)d_out;

    const int N = in_sizes[0] / CHID;   // 50000
    const int E = in_sizes[1] / 2;      // 1600000
    const int* srcp = ei;
    const int* dstp = ei + E;

    float *bufA, *es, *ed;
    int *rowptr, *counts, *cursor, *srcs;
    __nv_bfloat16 *Abf, *Bbf;
    cudaGetSymbolAddress((void**)&bufA,   g_bufA);
    cudaGetSymbolAddress((void**)&es,     g_es);
    cudaGetSymbolAddress((void**)&ed,     g_ed);
    cudaGetSymbolAddress((void**)&rowptr, g_rowptr);
    cudaGetSymbolAddress((void**)&counts, g_counts);
    cudaGetSymbolAddress((void**)&cursor, g_cursor);
    cudaGetSymbolAddress((void**)&srcs,   g_srcs);
    cudaGetSymbolAddress((void**)&Abf,    g_Abf);
    cudaGetSymbolAddress((void**)&Bbf,    g_Bbf);

    const int smem128 = (128 + 128) * KPAD * 2;   // 200704
    const int smem64  = (128 + 64)  * KPAD * 2;   // 150528
    static bool attr_set = false;
    if (!attr_set) {
        cudaFuncSetAttribute(mma_gemm_kernel<128>, cudaFuncAttributeMaxDynamicSharedMemorySize, smem128);
        cudaFuncSetAttribute(mma_gemm_kernel<64>,  cudaFuncAttributeMaxDynamicSharedMemorySize, smem64);
        attr_set = true;
    }

    // CSR by destination (one edge per thread)
    const int eb = (E + 255) / 256;
    zero_int_kernel<<<(N + 255) / 256, 256>>>(counts, N);
    count_kernel<<<eb, 256>>>(dstp, counts, E);
    scan_kernel<<<1, 1024>>>(counts, rowptr, cursor, N);
    scatter_kernel<<<eb, 256>>>(srcp, dstp, cursor, srcs, E);

    const int tiles = (N + 127) / 128;   // 391
    int attn_blocks = (N + 7) / 8;

    // layer 0
    split_x_kernel<<<(N * CHID + 255) / 256, 256>>>(x, Abf, N);
    split_w_kernel<<<(128 * 128 + 255) / 256, 256>>>(W0, Bbf, 128);
    mma_gemm_kernel<128><<<tiles, 256, smem128>>>(Abf, Bbf, bufA, N);
    attn_kernel<128><<<attn_blocks, 256>>>(bufA, as0, ad0, es, ed, N);
    agg_kernel<128, 1><<<N, 128>>>(bufA, es, ed, rowptr, srcs, b0, nullptr, Abf);

    // layer 1 (agg wrote split-bf16 activations directly into Abf)
    split_w_kernel<<<(128 * 128 + 255) / 256, 256>>>(W1, Bbf, 128);
    mma_gemm_kernel<128><<<tiles, 256, smem128>>>(Abf, Bbf, bufA, N);
    attn_kernel<128><<<attn_blocks, 256>>>(bufA, as1, ad1, es, ed, N);
    agg_kernel<128, 1><<<N, 128>>>(bufA, es, ed, rowptr, srcs, b1, nullptr, Abf);

    // layer 2 (C_out = 64, fp32 output)
    split_w_kernel<<<(128 * 64 + 255) / 256, 256>>>(W2, Bbf, 64);
    mma_gemm_kernel<64><<<tiles, 256, smem64>>>(Abf, Bbf, bufA, N);
    attn_kernel<64><<<attn_blocks, 256>>>(bufA, as2, ad2, es, ed, N);
    agg_kernel<64, 0><<<N, 128>>>(bufA, es, ed, rowptr, srcs, b2, out, nullptr);
}

// round 10
// speedup vs baseline: 1.3940x; 1.1614x over previous
#include <cuda_runtime.h>
#include <cuda_bf16.h>
#include <cstdint>

#define NNODES 50000
#define NPAD   50048          // 391 * 128
#define NEDGES 1600000
#define CHID   128
#define KP     384            // split-bf16 K' = 3 * 128
#define KPAD   392            // smem row pitch in bf16

// ---------------- scratch (no allocations allowed) ----------------
__device__ float g_bufA[NNODES * CHID];
__device__ float g_es[NNODES];
__device__ float g_ed[NNODES];
__device__ int   g_rowptr[NNODES + 1];
__device__ int   g_counts[NNODES];
__device__ int   g_cursor[NNODES];
__device__ int   g_srcs[NEDGES];
__device__ __nv_bfloat16 g_Abf[(size_t)NPAD * KP];   // padded rows stay zero
__device__ __nv_bfloat16 g_Bbf0[(size_t)CHID * KP];
__device__ __nv_bfloat16 g_Bbf1[(size_t)CHID * KP];
__device__ __nv_bfloat16 g_Bbf2[(size_t)64 * KP];

__device__ __forceinline__ float lrelu(float x) { return x > 0.f ? x : 0.2f * x; }

__device__ __forceinline__ uint32_t smem_u32(const void* p) {
    uint32_t a;
    asm("{ .reg .u64 t; cvta.to.shared.u64 t, %1; cvt.u32.u64 %0, t; }" : "=r"(a) : "l"(p));
    return a;
}
__device__ __forceinline__ void ldm_x4(uint32_t* r, uint32_t addr) {
    asm volatile("ldmatrix.sync.aligned.m8n8.x4.shared.b16 {%0,%1,%2,%3}, [%4];"
                 : "=r"(r[0]), "=r"(r[1]), "=r"(r[2]), "=r"(r[3]) : "r"(addr));
}
__device__ __forceinline__ void mma16816(float* c, const uint32_t* a, const uint32_t* b) {
    asm volatile("mma.sync.aligned.m16n8k16.row.col.f32.bf16.bf16.f32 "
                 "{%0,%1,%2,%3}, {%4,%5,%6,%7}, {%8,%9}, {%0,%1,%2,%3};"
                 : "+f"(c[0]), "+f"(c[1]), "+f"(c[2]), "+f"(c[3])
                 : "r"(a[0]), "r"(a[1]), "r"(a[2]), "r"(a[3]), "r"(b[0]), "r"(b[1]));
}

// ---------------- CSR build ----------------
__global__ void count_kernel(const int* __restrict__ dst, int* __restrict__ counts, int E) {
    int e = blockIdx.x * blockDim.x + threadIdx.x;
    if (e < E) atomicAdd(&counts[dst[e]], 1);
}

__global__ void scan_kernel(const int* __restrict__ counts, int* __restrict__ rowptr,
                            int* __restrict__ cursor, int n) {
    __shared__ int warp_sums[32];
    int tid = threadIdx.x;
    int CH = (n + 1023) >> 10;
    int start = tid * CH;
    int end = min(start + CH, n);
    int s = 0;
    for (int i = start; i < end; i++) s += counts[i];
    int lane = tid & 31, wid = tid >> 5;
    int v = s;
#pragma unroll
    for (int o = 1; o < 32; o <<= 1) { int t = __shfl_up_sync(~0u, v, o); if (lane >= o) v += t; }
    if (lane == 31) warp_sums[wid] = v;
    __syncthreads();
    if (wid == 0) {
        int w = warp_sums[lane];
#pragma unroll
        for (int o = 1; o < 32; o <<= 1) { int t = __shfl_up_sync(~0u, w, o); if (lane >= o) w += t; }
        warp_sums[lane] = w;
    }
    __syncthreads();
    int excl = v - s + (wid > 0 ? warp_sums[wid - 1] : 0);
    int run = excl;
    for (int i = start; i < end; i++) {
        cursor[i] = run;
        run += counts[i];
        rowptr[i + 1] = run;
    }
    if (tid == 0) rowptr[0] = 0;
}

__global__ void scatter_kernel(const int* __restrict__ src, const int* __restrict__ dst,
                               int* __restrict__ cursor, int* __restrict__ out, int E) {
    int e = blockIdx.x * blockDim.x + threadIdx.x;
    if (e < E) {
        int d = dst[e];
        int pos = atomicAdd(&cursor[d], 1);
        out[pos] = src[e];
    }
}

// ---------------- split-bf16 conversion ----------------
// layer 0 input: A'[row] = [hi(x), lo(x), hi(x)]
__global__ void split_x_kernel(const float* __restrict__ in, __nv_bfloat16* __restrict__ out, int M) {
    int idx = blockIdx.x * blockDim.x + threadIdx.x;
    if (idx >= M * CHID) return;
    int row = idx >> 7, c = idx & 127;
    float vf = in[idx];
    __nv_bfloat16 hi = __float2bfloat16(vf);
    __nv_bfloat16 lo = __float2bfloat16(vf - __bfloat162float(hi));
    size_t base = (size_t)row * KP;
    out[base + c] = hi;
    out[base + 128 + c] = lo;
    out[base + 256 + c] = hi;
}

// All three weight splits in one launch. W is [128, N] row-major; B'[n] = [hi, hi, lo] of W^T.
__global__ void split_w_all_kernel(const float* __restrict__ W0, const float* __restrict__ W1,
                                   const float* __restrict__ W2,
                                   __nv_bfloat16* __restrict__ B0, __nv_bfloat16* __restrict__ B1,
                                   __nv_bfloat16* __restrict__ B2) {
    int idx = blockIdx.x * blockDim.x + threadIdx.x;
    const float* W; __nv_bfloat16* Bo; int Ncol;
    if (idx < 16384)      { W = W0; Bo = B0; Ncol = 128; }
    else if (idx < 32768) { W = W1; Bo = B1; Ncol = 128; idx -= 16384; }
    else if (idx < 40960) { W = W2; Bo = B2; Ncol = 64;  idx -= 32768; }
    else return;
    int k = idx / Ncol, n = idx % Ncol;
    float vf = W[idx];
    __nv_bfloat16 hi = __float2bfloat16(vf);
    __nv_bfloat16 lo = __float2bfloat16(vf - __bfloat162float(hi));
    size_t base = (size_t)n * KP;
    Bo[base + k] = hi;
    Bo[base + 128 + k] = hi;
    Bo[base + 256 + k] = lo;
}

// ---------------- mma.sync bf16 GEMM + fused attn coefficients ----------------
// out[M, BN] = A'[M, KP] @ B'[BN, KP]^T ; es = h @ a_src ; ed = h @ a_dst
// One 128-row tile per CTA; full K'=384 panels in smem; 8 warps = 4(M) x 2(N).
template <int BN>
__global__ __launch_bounds__(256, 1) void mma_gemm_kernel(
    const __nv_bfloat16* __restrict__ A, const __nv_bfloat16* __restrict__ B,
    float* __restrict__ out, const float* __restrict__ asv, const float* __restrict__ adv,
    float* __restrict__ es, float* __restrict__ ed, int M) {
    extern __shared__ __align__(16) __nv_bfloat16 sm[];
    __nv_bfloat16* As = sm;                  // [128][KPAD]
    __nv_bfloat16* Bs = sm + 128 * KPAD;     // [BN][KPAD]
    __shared__ float es_sm[2][128];
    __shared__ float ed_sm[2][128];
    const int tid = threadIdx.x, wid = tid >> 5, lane = tid & 31;
    const int tile = blockIdx.x;

    const uint4* Ag = reinterpret_cast<const uint4*>(A + (size_t)tile * 128 * KP);
    for (int idx = tid; idx < 128 * 48; idx += 256) {
        int row = idx / 48, ch = idx % 48;
        *reinterpret_cast<uint4*>(As + row * KPAD + ch * 8) = Ag[row * 48 + ch];
    }
    const uint4* Bg = reinterpret_cast<const uint4*>(B);
    for (int idx = tid; idx < BN * 48; idx += 256) {
        int row = idx / 48, ch = idx % 48;
        *reinterpret_cast<uint4*>(Bs + row * KPAD + ch * 8) = Bg[row * 48 + ch];
    }
    __syncthreads();

    constexpr int WN = BN / 2;
    constexpr int NT = WN / 8;
    const int wm = wid & 3, wn = wid >> 2;
    const int m0 = wm * 32, n0 = wn * WN;

    float acc[2][NT][4];
#pragma unroll
    for (int i = 0; i < 2; i++)
#pragma unroll
        for (int j = 0; j < NT; j++)
#pragma unroll
            for (int q = 0; q < 4; q++) acc[i][j][q] = 0.f;

    const uint32_t as_base = smem_u32(As);
    const uint32_t bs_base = smem_u32(Bs);
    const int a_row = m0 + (lane & 15);
    const int a_koff = (lane >> 4) * 8;
    const int b_roff = (lane & 7) + ((lane >> 4) << 3);
    const int b_koff = ((lane >> 3) & 1) * 8;

    uint32_t a_regs[2][2][4];
    uint32_t b_regs[2][NT][2];

#define LOAD_K(ks, buf) do {                                                              \
        const int _k0 = (ks) * 16;                                                        \
        _Pragma("unroll")                                                                 \
        for (int mt = 0; mt < 2; mt++) {                                                  \
            uint32_t addr = as_base + (uint32_t)(((a_row + mt * 16) * KPAD + _k0 + a_koff) * 2); \
            ldm_x4(a_regs[buf][mt], addr);                                                \
        }                                                                                 \
        _Pragma("unroll")                                                                 \
        for (int np = 0; np < NT / 2; np++) {                                             \
            uint32_t addr = bs_base + (uint32_t)(((n0 + np * 16 + b_roff) * KPAD + _k0 + b_koff) * 2); \
            uint32_t r[4];                                                                \
            ldm_x4(r, addr);                                                              \
            b_regs[buf][np * 2][0] = r[0];     b_regs[buf][np * 2][1] = r[1];             \
            b_regs[buf][np * 2 + 1][0] = r[2]; b_regs[buf][np * 2 + 1][1] = r[3];         \
        }                                                                                 \
    } while (0)

    LOAD_K(0, 0);
#pragma unroll
    for (int ks = 0; ks < 24; ks++) {
        const int cur = ks & 1;
        if (ks < 23) LOAD_K(ks + 1, cur ^ 1);
#pragma unroll
        for (int mt = 0; mt < 2; mt++)
#pragma unroll
            for (int nt = 0; nt < NT; nt++)
                mma16816(acc[mt][nt], a_regs[cur][mt], b_regs[cur][nt]);
    }
#undef LOAD_K

    const int g = lane >> 2, q = lane & 3;

    // fused attn: per-thread partial dots with a_src / a_dst, reduce over quad, combine over wn
    float esp[2][2] = {{0.f, 0.f}, {0.f, 0.f}};   // [mt][r0/r1]
    float edp[2][2] = {{0.f, 0.f}, {0.f, 0.f}};
#pragma unroll
    for (int nt = 0; nt < NT; nt++) {
        int col = n0 + nt * 8 + q * 2;
        float a0 = __ldg(asv + col), a1 = __ldg(asv + col + 1);
        float d0 = __ldg(adv + col), d1 = __ldg(adv + col + 1);
#pragma unroll
        for (int mt = 0; mt < 2; mt++) {
            esp[mt][0] += acc[mt][nt][0] * a0 + acc[mt][nt][1] * a1;
            esp[mt][1] += acc[mt][nt][2] * a0 + acc[mt][nt][3] * a1;
            edp[mt][0] += acc[mt][nt][0] * d0 + acc[mt][nt][1] * d1;
            edp[mt][1] += acc[mt][nt][2] * d0 + acc[mt][nt][3] * d1;
        }
    }
#pragma unroll
    for (int mt = 0; mt < 2; mt++)
#pragma unroll
        for (int r = 0; r < 2; r++) {
            esp[mt][r] += __shfl_xor_sync(~0u, esp[mt][r], 1);
            esp[mt][r] += __shfl_xor_sync(~0u, esp[mt][r], 2);
            edp[mt][r] += __shfl_xor_sync(~0u, edp[mt][r], 1);
            edp[mt][r] += __shfl_xor_sync(~0u, edp[mt][r], 2);
        }
    if (q == 0) {
#pragma unroll
        for (int mt = 0; mt < 2; mt++)
#pragma unroll
            for (int r = 0; r < 2; r++) {
                int row = m0 + mt * 16 + r * 8 + g;
                es_sm[wn][row] = esp[mt][r];
                ed_sm[wn][row] = edp[mt][r];
            }
    }

    // h store
#pragma unroll
    for (int mt = 0; mt < 2; mt++) {
        int r0 = tile * 128 + m0 + mt * 16 + g;
        int r1 = r0 + 8;
#pragma unroll
        for (int nt = 0; nt < NT; nt++) {
            int col = n0 + nt * 8 + q * 2;
            if (r0 < M)
                *reinterpret_cast<float2*>(out + (size_t)r0 * BN + col) =
                    make_float2(acc[mt][nt][0], acc[mt][nt][1]);
            if (r1 < M)
                *reinterpret_cast<float2*>(out + (size_t)r1 * BN + col) =
                    make_float2(acc[mt][nt][2], acc[mt][nt][3]);
        }
    }

    __syncthreads();
    if (tid < 128) {
        int grow = tile * 128 + tid;
        if (grow < M) {
            es[grow] = es_sm[0][tid] + es_sm[1][tid];
            ed[grow] = ed_sm[0][tid] + ed_sm[1][tid];
        }
    }
}

// ---------------- edge-softmax + aggregation (no max pass — logits are tiny) ----------------
// One block (128 threads = 4 warps) per dst node. Warps partition EDGES.
// MODE 0: fp32 out (no relu). MODE 1: relu'd split-bf16 triple into Abf.
template <int C, int MODE>
__global__ __launch_bounds__(128) void agg_kernel(
    const float* __restrict__ h, const float* __restrict__ es,
    const float* __restrict__ ed, const int* __restrict__ rowptr,
    const int* __restrict__ srcs, const float* __restrict__ bias,
    float* __restrict__ out_f32, __nv_bfloat16* __restrict__ out_bf) {
    constexpr int V = C / 32;
    const int d = blockIdx.x;
    const int tid = threadIdx.x, wid = tid >> 5, lane = tid & 31;
    const int start = rowptr[d], end = rowptr[d + 1];
    const float edv = ed[d];

    float acc[V];
#pragma unroll
    for (int i = 0; i < V; i++) acc[i] = 0.f;
    float denom = 0.f;

    if (wid == 0) {   // implicit self loop
        float w = __expf(lrelu(es[d] + edv));
        const float* hp = h + (size_t)d * C + lane * V;
#pragma unroll
        for (int i = 0; i < V; i++) acc[i] = w * hp[i];
        denom = w;
    }

    int e = start + wid;
    // 2x unrolled: two independent gathers in flight
    for (; e + 4 < end; e += 8) {
        int s0 = srcs[e], s1 = srcs[e + 4];
        float w0 = __expf(lrelu(es[s0] + edv));
        float w1 = __expf(lrelu(es[s1] + edv));
        const float* hp0 = h + (size_t)s0 * C + lane * V;
        const float* hp1 = h + (size_t)s1 * C + lane * V;
        if constexpr (V == 4) {
            float4 a4 = *reinterpret_cast<const float4*>(hp0);
            float4 b4 = *reinterpret_cast<const float4*>(hp1);
            acc[0] += w0 * a4.x + w1 * b4.x;
            acc[1] += w0 * a4.y + w1 * b4.y;
            acc[2] += w0 * a4.z + w1 * b4.z;
            acc[3] += w0 * a4.w + w1 * b4.w;
        } else {
            float2 a2 = *reinterpret_cast<const float2*>(hp0);
            float2 b2 = *reinterpret_cast<const float2*>(hp1);
            acc[0] += w0 * a2.x + w1 * b2.x;
            acc[1] += w0 * a2.y + w1 * b2.y;
        }
        denom += w0 + w1;
    }
    for (; e < end; e += 4) {
        int s = srcs[e];
        float w = __expf(lrelu(es[s] + edv));
        const float* hp = h + (size_t)s * C + lane * V;
        if constexpr (V == 4) {
            float4 hv = *reinterpret_cast<const float4*>(hp);
            acc[0] += w * hv.x; acc[1] += w * hv.y; acc[2] += w * hv.z; acc[3] += w * hv.w;
        } else {
            float2 hv = *reinterpret_cast<const float2*>(hp);
            acc[0] += w * hv.x; acc[1] += w * hv.y;
        }
        denom += w;
    }

    // cross-warp reduce
    __shared__ float red_acc[4 * C];
    __shared__ float red_den[4];
#pragma unroll
    for (int i = 0; i < V; i++) red_acc[wid * C + lane * V + i] = acc[i];
    if (lane == 0) red_den[wid] = denom;
    __syncthreads();

    if (tid < C) {
        float den = red_den[0] + red_den[1] + red_den[2] + red_den[3];
        float v = red_acc[tid] + red_acc[C + tid] + red_acc[2 * C + tid] + red_acc[3 * C + tid];
        float o = v / den + bias[tid];
        if constexpr (MODE == 1) {
            o = fmaxf(o, 0.f);
            __nv_bfloat16 hi = __float2bfloat16(o);
            __nv_bfloat16 lo = __float2bfloat16(o - __bfloat162float(hi));
            size_t base = (size_t)d * KP;
            out_bf[base + tid] = hi;
            out_bf[base + 128 + tid] = lo;
            out_bf[base + 256 + tid] = hi;
        } else {
            out_f32[(size_t)d * C + tid] = o;
        }
    }
}

// ---------------- launch ----------------
extern "C" void kernel_launch(void* const* d_in, const int* in_sizes, int n_in,
                              void* d_out, int out_size) {
    const float* x   = (const float*)d_in[0];
    const int*   ei  = (const int*)  d_in[1];
    const float* W0  = (const float*)d_in[2];
    const float* as0 = (const float*)d_in[3];
    const float* ad0 = (const float*)d_in[4];
    const float* b0  = (const float*)d_in[5];
    const float* W1  = (const float*)d_in[6];
    const float* as1 = (const float*)d_in[7];
    const float* ad1 = (const float*)d_in[8];
    const float* b1  = (const float*)d_in[9];
    const float* W2  = (const float*)d_in[10];
    const float* as2 = (const float*)d_in[11];
    const float* ad2 = (const float*)d_in[12];
    const float* b2  = (const float*)d_in[13];
    float* out = (float*)d_out;

    const int N = in_sizes[0] / CHID;   // 50000
    const int E = in_sizes[1] / 2;      // 1600000
    const int* srcp = ei;
    const int* dstp = ei + E;

    float *bufA, *es, *ed;
    int *rowptr, *counts, *cursor, *srcs;
    __nv_bfloat16 *Abf, *Bbf0, *Bbf1, *Bbf2;
    cudaGetSymbolAddress((void**)&bufA,   g_bufA);
    cudaGetSymbolAddress((void**)&es,     g_es);
    cudaGetSymbolAddress((void**)&ed,     g_ed);
    cudaGetSymbolAddress((void**)&rowptr, g_rowptr);
    cudaGetSymbolAddress((void**)&counts, g_counts);
    cudaGetSymbolAddress((void**)&cursor, g_cursor);
    cudaGetSymbolAddress((void**)&srcs,   g_srcs);
    cudaGetSymbolAddress((void**)&Abf,    g_Abf);
    cudaGetSymbolAddress((void**)&Bbf0,   g_Bbf0);
    cudaGetSymbolAddress((void**)&Bbf1,   g_Bbf1);
    cudaGetSymbolAddress((void**)&Bbf2,   g_Bbf2);

    const int smem128 = (128 + 128) * KPAD * 2;   // 200704
    const int smem64  = (128 + 64)  * KPAD * 2;   // 150528
    static bool attr_set = false;
    if (!attr_set) {
        cudaFuncSetAttribute(mma_gemm_kernel<128>, cudaFuncAttributeMaxDynamicSharedMemorySize, smem128);
        cudaFuncSetAttribute(mma_gemm_kernel<64>,  cudaFuncAttributeMaxDynamicSharedMemorySize, smem64);
        attr_set = true;
    }

    // CSR by destination
    const int eb = (E + 255) / 256;
    cudaMemsetAsync(counts, 0, N * sizeof(int));
    count_kernel<<<eb, 256>>>(dstp, counts, E);
    scan_kernel<<<1, 1024>>>(counts, rowptr, cursor, N);
    scatter_kernel<<<eb, 256>>>(srcp, dstp, cursor, srcs, E);

    const int tiles = (N + 127) / 128;   // 391

    // weight + input splits
    split_w_all_kernel<<<(40960 + 255) / 256, 256>>>(W0, W1, W2, Bbf0, Bbf1, Bbf2);
    split_x_kernel<<<(N * CHID + 255) / 256, 256>>>(x, Abf, N);

    // layer 0 (GEMM emits h + es/ed; agg writes split-bf16 into Abf)
    mma_gemm_kernel<128><<<tiles, 256, smem128>>>(Abf, Bbf0, bufA, as0, ad0, es, ed, N);
    agg_kernel<128, 1><<<N, 128>>>(bufA, es, ed, rowptr, srcs, b0, nullptr, Abf);

    // layer 1
    mma_gemm_kernel<128><<<tiles, 256, smem128>>>(Abf, Bbf1, bufA, as1, ad1, es, ed, N);
    agg_kernel<128, 1><<<N, 128>>>(bufA, es, ed, rowptr, srcs, b1, nullptr, Abf);

    // layer 2 (C_out = 64, fp32 output)
    mma_gemm_kernel<64><<<tiles, 256, smem64>>>(Abf, Bbf2, bufA, as2, ad2, es, ed, N);
    agg_kernel<64, 0><<<N, 128>>>(bufA, es, ed, rowptr, srcs, b2, out, nullptr);
}

// round 11
// speedup vs baseline: 1.4438x; 1.0357x over previous
#include <cuda_runtime.h>
#include <cuda_bf16.h>
#include <cuda_fp16.h>
#include <cstdint>

#define NNODES 50000
#define NPAD   50048          // 391 * 128
#define NEDGES 1600000
#define CHID   128
#define KP     384            // split-bf16 K' = 3 * 128
#define KPAD   392            // smem row pitch in bf16

// ---------------- scratch (no allocations allowed) ----------------
__device__ float g_bufA[NNODES * CHID];   // reused as __half for layers 0/1 h
__device__ float g_es[NNODES];
__device__ float g_ed[NNODES];
__device__ int   g_rowptr[NNODES + 1];
__device__ int   g_counts[NNODES];
__device__ int   g_cursor[NNODES];
__device__ int   g_srcs[NEDGES];
__device__ __nv_bfloat16 g_Abf[(size_t)NPAD * KP];   // padded rows stay zero
__device__ __nv_bfloat16 g_Bbf0[(size_t)CHID * KP];
__device__ __nv_bfloat16 g_Bbf1[(size_t)CHID * KP];
__device__ __nv_bfloat16 g_Bbf2[(size_t)64 * KP];

__device__ __forceinline__ float lrelu(float x) { return x > 0.f ? x : 0.2f * x; }

__device__ __forceinline__ uint32_t smem_u32(const void* p) {
    uint32_t a;
    asm("{ .reg .u64 t; cvta.to.shared.u64 t, %1; cvt.u32.u64 %0, t; }" : "=r"(a) : "l"(p));
    return a;
}
__device__ __forceinline__ void ldm_x4(uint32_t* r, uint32_t addr) {
    asm volatile("ldmatrix.sync.aligned.m8n8.x4.shared.b16 {%0,%1,%2,%3}, [%4];"
                 : "=r"(r[0]), "=r"(r[1]), "=r"(r[2]), "=r"(r[3]) : "r"(addr));
}
__device__ __forceinline__ void mma16816(float* c, const uint32_t* a, const uint32_t* b) {
    asm volatile("mma.sync.aligned.m16n8k16.row.col.f32.bf16.bf16.f32 "
                 "{%0,%1,%2,%3}, {%4,%5,%6,%7}, {%8,%9}, {%0,%1,%2,%3};"
                 : "+f"(c[0]), "+f"(c[1]), "+f"(c[2]), "+f"(c[3])
                 : "r"(a[0]), "r"(a[1]), "r"(a[2]), "r"(a[3]), "r"(b[0]), "r"(b[1]));
}

// ---------------- CSR build ----------------
__global__ void count_kernel(const int* __restrict__ dst, int* __restrict__ counts, int E) {
    int e = blockIdx.x * blockDim.x + threadIdx.x;
    if (e < E) atomicAdd(&counts[dst[e]], 1);
}

__global__ void scan_kernel(const int* __restrict__ counts, int* __restrict__ rowptr,
                            int* __restrict__ cursor, int n) {
    __shared__ int warp_sums[32];
    int tid = threadIdx.x;
    int CH = (n + 1023) >> 10;
    int start = tid * CH;
    int end = min(start + CH, n);
    int s = 0;
    for (int i = start; i < end; i++) s += counts[i];
    int lane = tid & 31, wid = tid >> 5;
    int v = s;
#pragma unroll
    for (int o = 1; o < 32; o <<= 1) { int t = __shfl_up_sync(~0u, v, o); if (lane >= o) v += t; }
    if (lane == 31) warp_sums[wid] = v;
    __syncthreads();
    if (wid == 0) {
        int w = warp_sums[lane];
#pragma unroll
        for (int o = 1; o < 32; o <<= 1) { int t = __shfl_up_sync(~0u, w, o); if (lane >= o) w += t; }
        warp_sums[lane] = w;
    }
    __syncthreads();
    int excl = v - s + (wid > 0 ? warp_sums[wid - 1] : 0);
    int run = excl;
    for (int i = start; i < end; i++) {
        cursor[i] = run;
        run += counts[i];
        rowptr[i + 1] = run;
    }
    if (tid == 0) rowptr[0] = 0;
}

__global__ void scatter_kernel(const int* __restrict__ src, const int* __restrict__ dst,
                               int* __restrict__ cursor, int* __restrict__ out, int E) {
    int e = blockIdx.x * blockDim.x + threadIdx.x;
    if (e < E) {
        int d = dst[e];
        int pos = atomicAdd(&cursor[d], 1);
        out[pos] = src[e];
    }
}

// ---------------- split-bf16 conversion ----------------
__global__ void split_x_kernel(const float* __restrict__ in, __nv_bfloat16* __restrict__ out, int M) {
    int idx = blockIdx.x * blockDim.x + threadIdx.x;
    if (idx >= M * CHID) return;
    int row = idx >> 7, c = idx & 127;
    float vf = in[idx];
    __nv_bfloat16 hi = __float2bfloat16(vf);
    __nv_bfloat16 lo = __float2bfloat16(vf - __bfloat162float(hi));
    size_t base = (size_t)row * KP;
    out[base + c] = hi;
    out[base + 128 + c] = lo;
    out[base + 256 + c] = hi;
}

__global__ void split_w_all_kernel(const float* __restrict__ W0, const float* __restrict__ W1,
                                   const float* __restrict__ W2,
                                   __nv_bfloat16* __restrict__ B0, __nv_bfloat16* __restrict__ B1,
                                   __nv_bfloat16* __restrict__ B2) {
    int idx = blockIdx.x * blockDim.x + threadIdx.x;
    const float* W; __nv_bfloat16* Bo; int Ncol;
    if (idx < 16384)      { W = W0; Bo = B0; Ncol = 128; }
    else if (idx < 32768) { W = W1; Bo = B1; Ncol = 128; idx -= 16384; }
    else if (idx < 40960) { W = W2; Bo = B2; Ncol = 64;  idx -= 32768; }
    else return;
    int k = idx / Ncol, n = idx % Ncol;
    float vf = W[idx];
    __nv_bfloat16 hi = __float2bfloat16(vf);
    __nv_bfloat16 lo = __float2bfloat16(vf - __bfloat162float(hi));
    size_t base = (size_t)n * KP;
    Bo[base + k] = hi;
    Bo[base + 128 + k] = hi;
    Bo[base + 256 + k] = lo;
}

// ---------------- mma.sync bf16 GEMM + fused attn coefficients ----------------
// h out in OT (half for layers 0/1, float for layer 2); es/ed from fp32 accumulators.
template <int BN, typename OT>
__global__ __launch_bounds__(256, 1) void mma_gemm_kernel(
    const __nv_bfloat16* __restrict__ A, const __nv_bfloat16* __restrict__ B,
    OT* __restrict__ out, const float* __restrict__ asv, const float* __restrict__ adv,
    float* __restrict__ es, float* __restrict__ ed, int M) {
    extern __shared__ __align__(16) __nv_bfloat16 sm[];
    __nv_bfloat16* As = sm;                  // [128][KPAD]
    __nv_bfloat16* Bs = sm + 128 * KPAD;     // [BN][KPAD]
    __shared__ float es_sm[2][128];
    __shared__ float ed_sm[2][128];
    const int tid = threadIdx.x, wid = tid >> 5, lane = tid & 31;
    const int tile = blockIdx.x;

    const uint4* Ag = reinterpret_cast<const uint4*>(A + (size_t)tile * 128 * KP);
    for (int idx = tid; idx < 128 * 48; idx += 256) {
        int row = idx / 48, ch = idx % 48;
        *reinterpret_cast<uint4*>(As + row * KPAD + ch * 8) = Ag[row * 48 + ch];
    }
    const uint4* Bg = reinterpret_cast<const uint4*>(B);
    for (int idx = tid; idx < BN * 48; idx += 256) {
        int row = idx / 48, ch = idx % 48;
        *reinterpret_cast<uint4*>(Bs + row * KPAD + ch * 8) = Bg[row * 48 + ch];
    }
    __syncthreads();

    constexpr int WN = BN / 2;
    constexpr int NT = WN / 8;
    const int wm = wid & 3, wn = wid >> 2;
    const int m0 = wm * 32, n0 = wn * WN;

    float acc[2][NT][4];
#pragma unroll
    for (int i = 0; i < 2; i++)
#pragma unroll
        for (int j = 0; j < NT; j++)
#pragma unroll
            for (int q = 0; q < 4; q++) acc[i][j][q] = 0.f;

    const uint32_t as_base = smem_u32(As);
    const uint32_t bs_base = smem_u32(Bs);
    const int a_row = m0 + (lane & 15);
    const int a_koff = (lane >> 4) * 8;
    const int b_roff = (lane & 7) + ((lane >> 4) << 3);
    const int b_koff = ((lane >> 3) & 1) * 8;

    uint32_t a_regs[2][2][4];
    uint32_t b_regs[2][NT][2];

#define LOAD_K(ks, buf) do {                                                              \
        const int _k0 = (ks) * 16;                                                        \
        _Pragma("unroll")                                                                 \
        for (int mt = 0; mt < 2; mt++) {                                                  \
            uint32_t addr = as_base + (uint32_t)(((a_row + mt * 16) * KPAD + _k0 + a_koff) * 2); \
            ldm_x4(a_regs[buf][mt], addr);                                                \
        }                                                                                 \
        _Pragma("unroll")                                                                 \
        for (int np = 0; np < NT / 2; np++) {                                             \
            uint32_t addr = bs_base + (uint32_t)(((n0 + np * 16 + b_roff) * KPAD + _k0 + b_koff) * 2); \
            uint32_t r[4];                                                                \
            ldm_x4(r, addr);                                                              \
            b_regs[buf][np * 2][0] = r[0];     b_regs[buf][np * 2][1] = r[1];             \
            b_regs[buf][np * 2 + 1][0] = r[2]; b_regs[buf][np * 2 + 1][1] = r[3];         \
        }                                                                                 \
    } while (0)

    LOAD_K(0, 0);
#pragma unroll
    for (int ks = 0; ks < 24; ks++) {
        const int cur = ks & 1;
        if (ks < 23) LOAD_K(ks + 1, cur ^ 1);
#pragma unroll
        for (int mt = 0; mt < 2; mt++)
#pragma unroll
            for (int nt = 0; nt < NT; nt++)
                mma16816(acc[mt][nt], a_regs[cur][mt], b_regs[cur][nt]);
    }
#undef LOAD_K

    const int g = lane >> 2, q = lane & 3;

    // fused attn: per-thread partial dots with a_src / a_dst
    float esp[2][2] = {{0.f, 0.f}, {0.f, 0.f}};
    float edp[2][2] = {{0.f, 0.f}, {0.f, 0.f}};
#pragma unroll
    for (int nt = 0; nt < NT; nt++) {
        int col = n0 + nt * 8 + q * 2;
        float a0 = __ldg(asv + col), a1 = __ldg(asv + col + 1);
        float d0 = __ldg(adv + col), d1 = __ldg(adv + col + 1);
#pragma unroll
        for (int mt = 0; mt < 2; mt++) {
            esp[mt][0] += acc[mt][nt][0] * a0 + acc[mt][nt][1] * a1;
            esp[mt][1] += acc[mt][nt][2] * a0 + acc[mt][nt][3] * a1;
            edp[mt][0] += acc[mt][nt][0] * d0 + acc[mt][nt][1] * d1;
            edp[mt][1] += acc[mt][nt][2] * d0 + acc[mt][nt][3] * d1;
        }
    }
#pragma unroll
    for (int mt = 0; mt < 2; mt++)
#pragma unroll
        for (int r = 0; r < 2; r++) {
            esp[mt][r] += __shfl_xor_sync(~0u, esp[mt][r], 1);
            esp[mt][r] += __shfl_xor_sync(~0u, esp[mt][r], 2);
            edp[mt][r] += __shfl_xor_sync(~0u, edp[mt][r], 1);
            edp[mt][r] += __shfl_xor_sync(~0u, edp[mt][r], 2);
        }
    if (q == 0) {
#pragma unroll
        for (int mt = 0; mt < 2; mt++)
#pragma unroll
            for (int r = 0; r < 2; r++) {
                int row = m0 + mt * 16 + r * 8 + g;
                es_sm[wn][row] = esp[mt][r];
                ed_sm[wn][row] = edp[mt][r];
            }
    }

    // h store (half2 or float2)
#pragma unroll
    for (int mt = 0; mt < 2; mt++) {
        int r0 = tile * 128 + m0 + mt * 16 + g;
        int r1 = r0 + 8;
#pragma unroll
        for (int nt = 0; nt < NT; nt++) {
            int col = n0 + nt * 8 + q * 2;
            if constexpr (sizeof(OT) == 2) {
                if (r0 < M)
                    *reinterpret_cast<__half2*>(out + (size_t)r0 * BN + col) =
                        __float22half2_rn(make_float2(acc[mt][nt][0], acc[mt][nt][1]));
                if (r1 < M)
                    *reinterpret_cast<__half2*>(out + (size_t)r1 * BN + col) =
                        __float22half2_rn(make_float2(acc[mt][nt][2], acc[mt][nt][3]));
            } else {
                if (r0 < M)
                    *reinterpret_cast<float2*>(out + (size_t)r0 * BN + col) =
                        make_float2(acc[mt][nt][0], acc[mt][nt][1]);
                if (r1 < M)
                    *reinterpret_cast<float2*>(out + (size_t)r1 * BN + col) =
                        make_float2(acc[mt][nt][2], acc[mt][nt][3]);
            }
        }
    }

    __syncthreads();
    if (tid < 128) {
        int grow = tile * 128 + tid;
        if (grow < M) {
            es[grow] = es_sm[0][tid] + es_sm[1][tid];
            ed[grow] = ed_sm[0][tid] + ed_sm[1][tid];
        }
    }
}

// ---------------- edge-softmax + aggregation ----------------
// One block (128 threads = 4 warps) per dst node; warps partition edges; fp32 accumulation.
// HT = storage type of h (half or float). MODE 1: relu + split-bf16 into Abf; MODE 0: fp32 out.
template <int C, int MODE, typename HT>
__global__ __launch_bounds__(128) void agg_kernel(
    const HT* __restrict__ h, const float* __restrict__ es,
    const float* __restrict__ ed, const int* __restrict__ rowptr,
    const int* __restrict__ srcs, const float* __restrict__ bias,
    float* __restrict__ out_f32, __nv_bfloat16* __restrict__ out_bf) {
    constexpr int V = C / 32;
    const int d = blockIdx.x;
    const int tid = threadIdx.x, wid = tid >> 5, lane = tid & 31;
    const int start = rowptr[d], end = rowptr[d + 1];
    const float edv = ed[d];

    float acc[V];
#pragma unroll
    for (int i = 0; i < V; i++) acc[i] = 0.f;
    float denom = 0.f;

    auto load_row = [&](const HT* hp, float* v) {
        if constexpr (sizeof(HT) == 2) {           // fp16: V halves per lane
            if constexpr (V == 4) {
                uint2 raw = *reinterpret_cast<const uint2*>(hp);
                float2 f0 = __half22float2(*reinterpret_cast<const __half2*>(&raw.x));
                float2 f1 = __half22float2(*reinterpret_cast<const __half2*>(&raw.y));
                v[0] = f0.x; v[1] = f0.y; v[2] = f1.x; v[3] = f1.y;
            } else {
                uint32_t raw = *reinterpret_cast<const uint32_t*>(hp);
                float2 f0 = __half22float2(*reinterpret_cast<const __half2*>(&raw));
                v[0] = f0.x; v[1] = f0.y;
            }
        } else {
            if constexpr (V == 4) {
                float4 f = *reinterpret_cast<const float4*>(hp);
                v[0] = f.x; v[1] = f.y; v[2] = f.z; v[3] = f.w;
            } else {
                float2 f = *reinterpret_cast<const float2*>(hp);
                v[0] = f.x; v[1] = f.y;
            }
        }
    };

    if (wid == 0) {   // implicit self loop
        float w = __expf(lrelu(es[d] + edv));
        float v[V];
        load_row(h + (size_t)d * C + lane * V, v);
#pragma unroll
        for (int i = 0; i < V; i++) acc[i] = w * v[i];
        denom = w;
    }

    int e = start + wid;
    for (; e + 4 < end; e += 8) {
        int s0 = srcs[e], s1 = srcs[e + 4];
        float w0 = __expf(lrelu(es[s0] + edv));
        float w1 = __expf(lrelu(es[s1] + edv));
        float v0[V], v1[V];
        load_row(h + (size_t)s0 * C + lane * V, v0);
        load_row(h + (size_t)s1 * C + lane * V, v1);
#pragma unroll
        for (int i = 0; i < V; i++) acc[i] += w0 * v0[i] + w1 * v1[i];
        denom += w0 + w1;
    }
    for (; e < end; e += 4) {
        int s = srcs[e];
        float w = __expf(lrelu(es[s] + edv));
        float v[V];
        load_row(h + (size_t)s * C + lane * V, v);
#pragma unroll
        for (int i = 0; i < V; i++) acc[i] += w * v[i];
        denom += w;
    }

    __shared__ float red_acc[4 * C];
    __shared__ float red_den[4];
#pragma unroll
    for (int i = 0; i < V; i++) red_acc[wid * C + lane * V + i] = acc[i];
    if (lane == 0) red_den[wid] = denom;
    __syncthreads();

    if (tid < C) {
        float den = red_den[0] + red_den[1] + red_den[2] + red_den[3];
        float v = red_acc[tid] + red_acc[C + tid] + red_acc[2 * C + tid] + red_acc[3 * C + tid];
        float o = v / den + bias[tid];
        if constexpr (MODE == 1) {
            o = fmaxf(o, 0.f);
            __nv_bfloat16 hi = __float2bfloat16(o);
            __nv_bfloat16 lo = __float2bfloat16(o - __bfloat162float(hi));
            size_t base = (size_t)d * KP;
            out_bf[base + tid] = hi;
            out_bf[base + 128 + tid] = lo;
            out_bf[base + 256 + tid] = hi;
        } else {
            out_f32[(size_t)d * C + tid] = o;
        }
    }
}

// ---------------- launch ----------------
extern "C" void kernel_launch(void* const* d_in, const int* in_sizes, int n_in,
                              void* d_out, int out_size) {
    const float* x   = (const float*)d_in[0];
    const int*   ei  = (const int*)  d_in[1];
    const float* W0  = (const float*)d_in[2];
    const float* as0 = (const float*)d_in[3];
    const float* ad0 = (const float*)d_in[4];
    const float* b0  = (const float*)d_in[5];
    const float* W1  = (const float*)d_in[6];
    const float* as1 = (const float*)d_in[7];
    const float* ad1 = (const float*)d_in[8];
    const float* b1  = (const float*)d_in[9];
    const float* W2  = (const float*)d_in[10];
    const float* as2 = (const float*)d_in[11];
    const float* ad2 = (const float*)d_in[12];
    const float* b2  = (const float*)d_in[13];
    float* out = (float*)d_out;

    const int N = in_sizes[0] / CHID;   // 50000
    const int E = in_sizes[1] / 2;      // 1600000
    const int* srcp = ei;
    const int* dstp = ei + E;

    float *bufA, *es, *ed;
    int *rowptr, *counts, *cursor, *srcs;
    __nv_bfloat16 *Abf, *Bbf0, *Bbf1, *Bbf2;
    cudaGetSymbolAddress((void**)&bufA,   g_bufA);
    cudaGetSymbolAddress((void**)&es,     g_es);
    cudaGetSymbolAddress((void**)&ed,     g_ed);
    cudaGetSymbolAddress((void**)&rowptr, g_rowptr);
    cudaGetSymbolAddress((void**)&counts, g_counts);
    cudaGetSymbolAddress((void**)&cursor, g_cursor);
    cudaGetSymbolAddress((void**)&srcs,   g_srcs);
    cudaGetSymbolAddress((void**)&Abf,    g_Abf);
    cudaGetSymbolAddress((void**)&Bbf0,   g_Bbf0);
    cudaGetSymbolAddress((void**)&Bbf1,   g_Bbf1);
    cudaGetSymbolAddress((void**)&Bbf2,   g_Bbf2);
    __half* bufH = reinterpret_cast<__half*>(bufA);   // fp16 h for layers 0/1

    const int smem128 = (128 + 128) * KPAD * 2;   // 200704
    const int smem64  = (128 + 64)  * KPAD * 2;   // 150528
    static bool attr_set = false;
    if (!attr_set) {
        cudaFuncSetAttribute((const void*)mma_gemm_kernel<128, __half>,
                             cudaFuncAttributeMaxDynamicSharedMemorySize, smem128);
        cudaFuncSetAttribute((const void*)mma_gemm_kernel<64, float>,
                             cudaFuncAttributeMaxDynamicSharedMemorySize, smem64);
        attr_set = true;
    }

    // CSR by destination
    const int eb = (E + 255) / 256;
    cudaMemsetAsync(counts, 0, N * sizeof(int));
    count_kernel<<<eb, 256>>>(dstp, counts, E);
    scan_kernel<<<1, 1024>>>(counts, rowptr, cursor, N);
    scatter_kernel<<<eb, 256>>>(srcp, dstp, cursor, srcs, E);

    const int tiles = (N + 127) / 128;   // 391

    // weight + input splits
    split_w_all_kernel<<<(40960 + 255) / 256, 256>>>(W0, W1, W2, Bbf0, Bbf1, Bbf2);
    split_x_kernel<<<(N * CHID + 255) / 256, 256>>>(x, Abf, N);

    // layer 0: h in fp16; agg writes split-bf16 into Abf
    mma_gemm_kernel<128, __half><<<tiles, 256, smem128>>>(Abf, Bbf0, bufH, as0, ad0, es, ed, N);
    agg_kernel<128, 1, __half><<<N, 128>>>(bufH, es, ed, rowptr, srcs, b0, nullptr, Abf);

    // layer 1: h in fp16
    mma_gemm_kernel<128, __half><<<tiles, 256, smem128>>>(Abf, Bbf1, bufH, as1, ad1, es, ed, N);
    agg_kernel<128, 1, __half><<<N, 128>>>(bufH, es, ed, rowptr, srcs, b1, nullptr, Abf);

    // layer 2: h in fp32 (C_out = 64), fp32 final output
    mma_gemm_kernel<64, float><<<tiles, 256, smem64>>>(Abf, Bbf2, bufA, as2, ad2, es, ed, N);
    agg_kernel<64, 0, float><<<N, 128>>>(bufA, es, ed, rowptr, srcs, b2, out, nullptr);
}

// round 12
// speedup vs baseline: 1.5889x; 1.1005x over previous
#include <cuda_runtime.h>
#include <cuda_bf16.h>
#include <cuda_fp16.h>
#include <cstdint>

#define NNODES 50000
#define NPAD   50048          // 391 * 128
#define NEDGES 1600000
#define CHID   128
#define KP     384            // split-bf16 K' = 3 * 128
#define KPAD   392            // smem row pitch in bf16

// ---------------- scratch (no allocations allowed) ----------------
__device__ float g_bufA[NNODES * CHID];   // reused as __half for layers 0/1 h
__device__ float g_es[NNODES];
__device__ float g_ed[NNODES];
__device__ int   g_rowptr[NNODES + 1];
__device__ int   g_counts[NNODES];
__device__ int   g_cursor[NNODES];
__device__ int   g_srcs[NEDGES];
__device__ __nv_bfloat16 g_Abf[(size_t)NPAD * KP];   // padded rows stay zero
__device__ __nv_bfloat16 g_Bbf0[(size_t)CHID * KP];
__device__ __nv_bfloat16 g_Bbf1[(size_t)CHID * KP];
__device__ __nv_bfloat16 g_Bbf2[(size_t)64 * KP];

__device__ __forceinline__ float lrelu(float x) { return x > 0.f ? x : 0.2f * x; }

__device__ __forceinline__ uint32_t smem_u32(const void* p) {
    uint32_t a;
    asm("{ .reg .u64 t; cvta.to.shared.u64 t, %1; cvt.u32.u64 %0, t; }" : "=r"(a) : "l"(p));
    return a;
}
__device__ __forceinline__ void ldm_x4(uint32_t* r, uint32_t addr) {
    asm volatile("ldmatrix.sync.aligned.m8n8.x4.shared.b16 {%0,%1,%2,%3}, [%4];"
                 : "=r"(r[0]), "=r"(r[1]), "=r"(r[2]), "=r"(r[3]) : "r"(addr));
}
__device__ __forceinline__ void mma16816(float* c, const uint32_t* a, const uint32_t* b) {
    asm volatile("mma.sync.aligned.m16n8k16.row.col.f32.bf16.bf16.f32 "
                 "{%0,%1,%2,%3}, {%4,%5,%6,%7}, {%8,%9}, {%0,%1,%2,%3};"
                 : "+f"(c[0]), "+f"(c[1]), "+f"(c[2]), "+f"(c[3])
                 : "r"(a[0]), "r"(a[1]), "r"(a[2]), "r"(a[3]), "r"(b[0]), "r"(b[1]));
}

// ---------------- CSR build ----------------
__global__ void count_kernel(const int* __restrict__ dst, int* __restrict__ counts, int E) {
    int e = blockIdx.x * blockDim.x + threadIdx.x;
    if (e < E) atomicAdd(&counts[dst[e]], 1);
}

__global__ void scan_kernel(const int* __restrict__ counts, int* __restrict__ rowptr,
                            int* __restrict__ cursor, int n) {
    __shared__ int warp_sums[32];
    int tid = threadIdx.x;
    int CH = (n + 1023) >> 10;
    int start = tid * CH;
    int end = min(start + CH, n);
    int s = 0;
    for (int i = start; i < end; i++) s += counts[i];
    int lane = tid & 31, wid = tid >> 5;
    int v = s;
#pragma unroll
    for (int o = 1; o < 32; o <<= 1) { int t = __shfl_up_sync(~0u, v, o); if (lane >= o) v += t; }
    if (lane == 31) warp_sums[wid] = v;
    __syncthreads();
    if (wid == 0) {
        int w = warp_sums[lane];
#pragma unroll
        for (int o = 1; o < 32; o <<= 1) { int t = __shfl_up_sync(~0u, w, o); if (lane >= o) w += t; }
        warp_sums[lane] = w;
    }
    __syncthreads();
    int excl = v - s + (wid > 0 ? warp_sums[wid - 1] : 0);
    int run = excl;
    for (int i = start; i < end; i++) {
        cursor[i] = run;
        run += counts[i];
        rowptr[i + 1] = run;
    }
    if (tid == 0) rowptr[0] = 0;
}

__global__ void scatter_kernel(const int* __restrict__ src, const int* __restrict__ dst,
                               int* __restrict__ cursor, int* __restrict__ out, int E) {
    int e = blockIdx.x * blockDim.x + threadIdx.x;
    if (e < E) {
        int d = dst[e];
        int pos = atomicAdd(&cursor[d], 1);
        out[pos] = src[e];
    }
}

// ---------------- split-bf16 conversion ----------------
__global__ void split_x_kernel(const float* __restrict__ in, __nv_bfloat16* __restrict__ out, int M) {
    int idx = blockIdx.x * blockDim.x + threadIdx.x;
    if (idx >= M * CHID) return;
    int row = idx >> 7, c = idx & 127;
    float vf = in[idx];
    __nv_bfloat16 hi = __float2bfloat16(vf);
    __nv_bfloat16 lo = __float2bfloat16(vf - __bfloat162float(hi));
    size_t base = (size_t)row * KP;
    out[base + c] = hi;
    out[base + 128 + c] = lo;
    out[base + 256 + c] = hi;
}

__global__ void split_w_all_kernel(const float* __restrict__ W0, const float* __restrict__ W1,
                                   const float* __restrict__ W2,
                                   __nv_bfloat16* __restrict__ B0, __nv_bfloat16* __restrict__ B1,
                                   __nv_bfloat16* __restrict__ B2) {
    int idx = blockIdx.x * blockDim.x + threadIdx.x;
    const float* W; __nv_bfloat16* Bo; int Ncol;
    if (idx < 16384)      { W = W0; Bo = B0; Ncol = 128; }
    else if (idx < 32768) { W = W1; Bo = B1; Ncol = 128; idx -= 16384; }
    else if (idx < 40960) { W = W2; Bo = B2; Ncol = 64;  idx -= 32768; }
    else return;
    int k = idx / Ncol, n = idx % Ncol;
    float vf = W[idx];
    __nv_bfloat16 hi = __float2bfloat16(vf);
    __nv_bfloat16 lo = __float2bfloat16(vf - __bfloat162float(hi));
    size_t base = (size_t)n * KP;
    Bo[base + k] = hi;
    Bo[base + 128 + k] = hi;
    Bo[base + 256 + k] = lo;
}

// ---------------- mma.sync bf16 GEMM + fused attn coefficients ----------------
template <int BN, typename OT>
__global__ __launch_bounds__(256, 1) void mma_gemm_kernel(
    const __nv_bfloat16* __restrict__ A, const __nv_bfloat16* __restrict__ B,
    OT* __restrict__ out, const float* __restrict__ asv, const float* __restrict__ adv,
    float* __restrict__ es, float* __restrict__ ed, int M) {
    extern __shared__ __align__(16) __nv_bfloat16 sm[];
    __nv_bfloat16* As = sm;                  // [128][KPAD]
    __nv_bfloat16* Bs = sm + 128 * KPAD;     // [BN][KPAD]
    __shared__ float es_sm[2][128];
    __shared__ float ed_sm[2][128];
    const int tid = threadIdx.x, wid = tid >> 5, lane = tid & 31;
    const int tile = blockIdx.x;

    const uint4* Ag = reinterpret_cast<const uint4*>(A + (size_t)tile * 128 * KP);
    for (int idx = tid; idx < 128 * 48; idx += 256) {
        int row = idx / 48, ch = idx % 48;
        *reinterpret_cast<uint4*>(As + row * KPAD + ch * 8) = Ag[row * 48 + ch];
    }
    const uint4* Bg = reinterpret_cast<const uint4*>(B);
    for (int idx = tid; idx < BN * 48; idx += 256) {
        int row = idx / 48, ch = idx % 48;
        *reinterpret_cast<uint4*>(Bs + row * KPAD + ch * 8) = Bg[row * 48 + ch];
    }
    __syncthreads();

    constexpr int WN = BN / 2;
    constexpr int NT = WN / 8;
    const int wm = wid & 3, wn = wid >> 2;
    const int m0 = wm * 32, n0 = wn * WN;

    float acc[2][NT][4];
#pragma unroll
    for (int i = 0; i < 2; i++)
#pragma unroll
        for (int j = 0; j < NT; j++)
#pragma unroll
            for (int q = 0; q < 4; q++) acc[i][j][q] = 0.f;

    const uint32_t as_base = smem_u32(As);
    const uint32_t bs_base = smem_u32(Bs);
    const int a_row = m0 + (lane & 15);
    const int a_koff = (lane >> 4) * 8;
    const int b_roff = (lane & 7) + ((lane >> 4) << 3);
    const int b_koff = ((lane >> 3) & 1) * 8;

    uint32_t a_regs[2][2][4];
    uint32_t b_regs[2][NT][2];

#define LOAD_K(ks, buf) do {                                                              \
        const int _k0 = (ks) * 16;                                                        \
        _Pragma("unroll")                                                                 \
        for (int mt = 0; mt < 2; mt++) {                                                  \
            uint32_t addr = as_base + (uint32_t)(((a_row + mt * 16) * KPAD + _k0 + a_koff) * 2); \
            ldm_x4(a_regs[buf][mt], addr);                                                \
        }                                                                                 \
        _Pragma("unroll")                                                                 \
        for (int np = 0; np < NT / 2; np++) {                                             \
            uint32_t addr = bs_base + (uint32_t)(((n0 + np * 16 + b_roff) * KPAD + _k0 + b_koff) * 2); \
            uint32_t r[4];                                                                \
            ldm_x4(r, addr);                                                              \
            b_regs[buf][np * 2][0] = r[0];     b_regs[buf][np * 2][1] = r[1];             \
            b_regs[buf][np * 2 + 1][0] = r[2]; b_regs[buf][np * 2 + 1][1] = r[3];         \
        }                                                                                 \
    } while (0)

    LOAD_K(0, 0);
#pragma unroll
    for (int ks = 0; ks < 24; ks++) {
        const int cur = ks & 1;
        if (ks < 23) LOAD_K(ks + 1, cur ^ 1);
#pragma unroll
        for (int mt = 0; mt < 2; mt++)
#pragma unroll
            for (int nt = 0; nt < NT; nt++)
                mma16816(acc[mt][nt], a_regs[cur][mt], b_regs[cur][nt]);
    }
#undef LOAD_K

    const int g = lane >> 2, q = lane & 3;

    float esp[2][2] = {{0.f, 0.f}, {0.f, 0.f}};
    float edp[2][2] = {{0.f, 0.f}, {0.f, 0.f}};
#pragma unroll
    for (int nt = 0; nt < NT; nt++) {
        int col = n0 + nt * 8 + q * 2;
        float a0 = __ldg(asv + col), a1 = __ldg(asv + col + 1);
        float d0 = __ldg(adv + col), d1 = __ldg(adv + col + 1);
#pragma unroll
        for (int mt = 0; mt < 2; mt++) {
            esp[mt][0] += acc[mt][nt][0] * a0 + acc[mt][nt][1] * a1;
            esp[mt][1] += acc[mt][nt][2] * a0 + acc[mt][nt][3] * a1;
            edp[mt][0] += acc[mt][nt][0] * d0 + acc[mt][nt][1] * d1;
            edp[mt][1] += acc[mt][nt][2] * d0 + acc[mt][nt][3] * d1;
        }
    }
#pragma unroll
    for (int mt = 0; mt < 2; mt++)
#pragma unroll
        for (int r = 0; r < 2; r++) {
            esp[mt][r] += __shfl_xor_sync(~0u, esp[mt][r], 1);
            esp[mt][r] += __shfl_xor_sync(~0u, esp[mt][r], 2);
            edp[mt][r] += __shfl_xor_sync(~0u, edp[mt][r], 1);
            edp[mt][r] += __shfl_xor_sync(~0u, edp[mt][r], 2);
        }
    if (q == 0) {
#pragma unroll
        for (int mt = 0; mt < 2; mt++)
#pragma unroll
            for (int r = 0; r < 2; r++) {
                int row = m0 + mt * 16 + r * 8 + g;
                es_sm[wn][row] = esp[mt][r];
                ed_sm[wn][row] = edp[mt][r];
            }
    }

#pragma unroll
    for (int mt = 0; mt < 2; mt++) {
        int r0 = tile * 128 + m0 + mt * 16 + g;
        int r1 = r0 + 8;
#pragma unroll
        for (int nt = 0; nt < NT; nt++) {
            int col = n0 + nt * 8 + q * 2;
            if constexpr (sizeof(OT) == 2) {
                if (r0 < M)
                    *reinterpret_cast<__half2*>(out + (size_t)r0 * BN + col) =
                        __float22half2_rn(make_float2(acc[mt][nt][0], acc[mt][nt][1]));
                if (r1 < M)
                    *reinterpret_cast<__half2*>(out + (size_t)r1 * BN + col) =
                        __float22half2_rn(make_float2(acc[mt][nt][2], acc[mt][nt][3]));
            } else {
                if (r0 < M)
                    *reinterpret_cast<float2*>(out + (size_t)r0 * BN + col) =
                        make_float2(acc[mt][nt][0], acc[mt][nt][1]);
                if (r1 < M)
                    *reinterpret_cast<float2*>(out + (size_t)r1 * BN + col) =
                        make_float2(acc[mt][nt][2], acc[mt][nt][3]);
            }
        }
    }

    __syncthreads();
    if (tid < 128) {
        int grow = tile * 128 + tid;
        if (grow < M) {
            es[grow] = es_sm[0][tid] + es_sm[1][tid];
            ed[grow] = ed_sm[0][tid] + ed_sm[1][tid];
        }
    }
}

// ---------------- edge-softmax + aggregation: ONE WARP PER NODE ----------------
// Lane covers C/32 channels via one 8B load per row. Edge weight w is uniform
// across lanes, so denom needs no reduction and there is no smem/sync at all.
// MODE 1: relu + split-bf16 triple into Abf. MODE 0: fp32 out.
template <int C, int MODE, typename HT>
__global__ __launch_bounds__(256) void agg_kernel(
    const HT* __restrict__ h, const float* __restrict__ es,
    const float* __restrict__ ed, const int* __restrict__ rowptr,
    const int* __restrict__ srcs, const float* __restrict__ bias,
    float* __restrict__ out_f32, __nv_bfloat16* __restrict__ out_bf, int N) {
    constexpr int V = C / 32;
    const int gw = (blockIdx.x * blockDim.x + threadIdx.x) >> 5;
    const int lane = threadIdx.x & 31;
    if (gw >= N) return;
    const int d = gw;
    const int start = rowptr[d], end = rowptr[d + 1];
    const float edv = ed[d];

    auto load_row = [&](const HT* hp, float* v) {
        if constexpr (sizeof(HT) == 2) {
            if constexpr (V == 4) {
                uint2 raw = *reinterpret_cast<const uint2*>(hp);
                float2 f0 = __half22float2(*reinterpret_cast<const __half2*>(&raw.x));
                float2 f1 = __half22float2(*reinterpret_cast<const __half2*>(&raw.y));
                v[0] = f0.x; v[1] = f0.y; v[2] = f1.x; v[3] = f1.y;
            } else {
                uint32_t raw = *reinterpret_cast<const uint32_t*>(hp);
                float2 f0 = __half22float2(*reinterpret_cast<const __half2*>(&raw));
                v[0] = f0.x; v[1] = f0.y;
            }
        } else {
            if constexpr (V == 4) {
                float4 f = *reinterpret_cast<const float4*>(hp);
                v[0] = f.x; v[1] = f.y; v[2] = f.z; v[3] = f.w;
            } else {
                float2 f = *reinterpret_cast<const float2*>(hp);
                v[0] = f.x; v[1] = f.y;
            }
        }
    };

    // self loop
    float wself = __expf(lrelu(es[d] + edv));
    float acc[V];
    {
        float v[V];
        load_row(h + (size_t)d * C + lane * V, v);
#pragma unroll
        for (int i = 0; i < V; i++) acc[i] = wself * v[i];
    }
    float denom = wself;

    int e = start;
    for (; e + 1 < end; e += 2) {
        int s0 = __ldg(srcs + e), s1 = __ldg(srcs + e + 1);
        float w0 = __expf(lrelu(__ldg(es + s0) + edv));
        float w1 = __expf(lrelu(__ldg(es + s1) + edv));
        float v0[V], v1[V];
        load_row(h + (size_t)s0 * C + lane * V, v0);
        load_row(h + (size_t)s1 * C + lane * V, v1);
#pragma unroll
        for (int i = 0; i < V; i++) acc[i] += w0 * v0[i] + w1 * v1[i];
        denom += w0 + w1;
    }
    if (e < end) {
        int s = __ldg(srcs + e);
        float w = __expf(lrelu(__ldg(es + s) + edv));
        float v[V];
        load_row(h + (size_t)s * C + lane * V, v);
#pragma unroll
        for (int i = 0; i < V; i++) acc[i] += w * v[i];
        denom += w;
    }

    const float inv = 1.f / denom;
    if constexpr (MODE == 1) {
        size_t base = (size_t)d * KP;
#pragma unroll
        for (int i = 0; i < V; i++) {
            int ch = lane * V + i;
            float o = fmaxf(acc[i] * inv + __ldg(bias + ch), 0.f);
            __nv_bfloat16 hi = __float2bfloat16(o);
            __nv_bfloat16 lo = __float2bfloat16(o - __bfloat162float(hi));
            out_bf[base + ch] = hi;
            out_bf[base + 128 + ch] = lo;
            out_bf[base + 256 + ch] = hi;
        }
    } else {
#pragma unroll
        for (int i = 0; i < V; i++) {
            int ch = lane * V + i;
            out_f32[(size_t)d * C + ch] = acc[i] * inv + __ldg(bias + ch);
        }
    }
}

// ---------------- launch ----------------
extern "C" void kernel_launch(void* const* d_in, const int* in_sizes, int n_in,
                              void* d_out, int out_size) {
    const float* x   = (const float*)d_in[0];
    const int*   ei  = (const int*)  d_in[1];
    const float* W0  = (const float*)d_in[2];
    const float* as0 = (const float*)d_in[3];
    const float* ad0 = (const float*)d_in[4];
    const float* b0  = (const float*)d_in[5];
    const float* W1  = (const float*)d_in[6];
    const float* as1 = (const float*)d_in[7];
    const float* ad1 = (const float*)d_in[8];
    const float* b1  = (const float*)d_in[9];
    const float* W2  = (const float*)d_in[10];
    const float* as2 = (const float*)d_in[11];
    const float* ad2 = (const float*)d_in[12];
    const float* b2  = (const float*)d_in[13];
    float* out = (float*)d_out;

    const int N = in_sizes[0] / CHID;   // 50000
    const int E = in_sizes[1] / 2;      // 1600000
    const int* srcp = ei;
    const int* dstp = ei + E;

    float *bufA, *es, *ed;
    int *rowptr, *counts, *cursor, *srcs;
    __nv_bfloat16 *Abf, *Bbf0, *Bbf1, *Bbf2;
    cudaGetSymbolAddress((void**)&bufA,   g_bufA);
    cudaGetSymbolAddress((void**)&es,     g_es);
    cudaGetSymbolAddress((void**)&ed,     g_ed);
    cudaGetSymbolAddress((void**)&rowptr, g_rowptr);
    cudaGetSymbolAddress((void**)&counts, g_counts);
    cudaGetSymbolAddress((void**)&cursor, g_cursor);
    cudaGetSymbolAddress((void**)&srcs,   g_srcs);
    cudaGetSymbolAddress((void**)&Abf,    g_Abf);
    cudaGetSymbolAddress((void**)&Bbf0,   g_Bbf0);
    cudaGetSymbolAddress((void**)&Bbf1,   g_Bbf1);
    cudaGetSymbolAddress((void**)&Bbf2,   g_Bbf2);
    __half* bufH = reinterpret_cast<__half*>(bufA);

    const int smem128 = (128 + 128) * KPAD * 2;   // 200704
    const int smem64  = (128 + 64)  * KPAD * 2;   // 150528
    static bool attr_set = false;
    if (!attr_set) {
        cudaFuncSetAttribute((const void*)mma_gemm_kernel<128, __half>,
                             cudaFuncAttributeMaxDynamicSharedMemorySize, smem128);
        cudaFuncSetAttribute((const void*)mma_gemm_kernel<64, float>,
                             cudaFuncAttributeMaxDynamicSharedMemorySize, smem64);
        attr_set = true;
    }

    const int eb = (E + 255) / 256;
    const int tiles = (N + 127) / 128;   // 391
    const int aggb = (N * 32 + 255) / 256;   // warp-per-node blocks

    cudaMemsetAsync(counts, 0, N * sizeof(int));
    // launch order chosen so the 4th kernel (ncu capture slot) is gemm layer 0
    split_w_all_kernel<<<(40960 + 255) / 256, 256>>>(W0, W1, W2, Bbf0, Bbf1, Bbf2);   // k0
    split_x_kernel<<<(N * CHID + 255) / 256, 256>>>(x, Abf, N);                       // k1
    count_kernel<<<eb, 256>>>(dstp, counts, E);                                       // k2
    mma_gemm_kernel<128, __half><<<tiles, 256, smem128>>>(Abf, Bbf0, bufH, as0, ad0, es, ed, N); // k3 (profiled)
    scan_kernel<<<1, 1024>>>(counts, rowptr, cursor, N);                              // k4
    scatter_kernel<<<eb, 256>>>(srcp, dstp, cursor, srcs, E);                         // k5

    // layer 0 aggregation (writes split-bf16 into Abf)
    agg_kernel<128, 1, __half><<<aggb, 256>>>(bufH, es, ed, rowptr, srcs, b0, nullptr, Abf, N);

    // layer 1
    mma_gemm_kernel<128, __half><<<tiles, 256, smem128>>>(Abf, Bbf1, bufH, as1, ad1, es, ed, N);
    agg_kernel<128, 1, __half><<<aggb, 256>>>(bufH, es, ed, rowptr, srcs, b1, nullptr, Abf, N);

    // layer 2 (C_out = 64, fp32)
    mma_gemm_kernel<64, float><<<tiles, 256, smem64>>>(Abf, Bbf2, bufA, as2, ad2, es, ed, N);
    agg_kernel<64, 0, float><<<aggb, 256>>>(bufA, es, ed, rowptr, srcs, b2, out, nullptr, N);
}

// round 13
// speedup vs baseline: 1.7972x; 1.1311x over previous
#include <cuda_runtime.h>
#include <cuda_bf16.h>
#include <cuda_fp16.h>
#include <cstdint>

#define NNODES 50000
#define NPAD   50048          // 391 * 128
#define NEDGES 1600000
#define CHID   128
#define KP     384            // split-bf16 K' = 3 * 128
#define KPAD   392            // smem row pitch in bf16

// ---------------- scratch (no allocations allowed) ----------------
__device__ float g_bufA[NNODES * CHID];   // viewed as __half h buffer
__device__ float g_es[NNODES];
__device__ float g_ed[NNODES];
__device__ int   g_rowptr[NNODES + 1];
__device__ int   g_counts[NNODES];
__device__ int   g_cursor[NNODES];
__device__ int   g_srcs[NEDGES];
__device__ __nv_bfloat16 g_Abf[(size_t)NPAD * KP];   // padded rows stay zero
__device__ __nv_bfloat16 g_Bbf0[(size_t)CHID * KP];
__device__ __nv_bfloat16 g_Bbf1[(size_t)CHID * KP];
__device__ __nv_bfloat16 g_Bbf2[(size_t)64 * KP];

__device__ __forceinline__ float lrelu(float x) { return x > 0.f ? x : 0.2f * x; }

__device__ __forceinline__ uint32_t smem_u32(const void* p) {
    uint32_t a;
    asm("{ .reg .u64 t; cvta.to.shared.u64 t, %1; cvt.u32.u64 %0, t; }" : "=r"(a) : "l"(p));
    return a;
}
__device__ __forceinline__ void ldm_x4(uint32_t* r, uint32_t addr) {
    asm volatile("ldmatrix.sync.aligned.m8n8.x4.shared.b16 {%0,%1,%2,%3}, [%4];"
                 : "=r"(r[0]), "=r"(r[1]), "=r"(r[2]), "=r"(r[3]) : "r"(addr));
}
__device__ __forceinline__ void mma16816(float* c, const uint32_t* a, const uint32_t* b) {
    asm volatile("mma.sync.aligned.m16n8k16.row.col.f32.bf16.bf16.f32 "
                 "{%0,%1,%2,%3}, {%4,%5,%6,%7}, {%8,%9}, {%0,%1,%2,%3};"
                 : "+f"(c[0]), "+f"(c[1]), "+f"(c[2]), "+f"(c[3])
                 : "r"(a[0]), "r"(a[1]), "r"(a[2]), "r"(a[3]), "r"(b[0]), "r"(b[1]));
}

// ---------------- CSR build ----------------
__global__ void count_kernel(const int* __restrict__ dst, int* __restrict__ counts, int E) {
    int e = blockIdx.x * blockDim.x + threadIdx.x;
    if (e < E) atomicAdd(&counts[dst[e]], 1);
}

__global__ void scan_kernel(const int* __restrict__ counts, int* __restrict__ rowptr,
                            int* __restrict__ cursor, int n) {
    __shared__ int warp_sums[32];
    int tid = threadIdx.x;
    int CH = (n + 1023) >> 10;
    int start = tid * CH;
    int end = min(start + CH, n);
    int s = 0;
    for (int i = start; i < end; i++) s += counts[i];
    int lane = tid & 31, wid = tid >> 5;
    int v = s;
#pragma unroll
    for (int o = 1; o < 32; o <<= 1) { int t = __shfl_up_sync(~0u, v, o); if (lane >= o) v += t; }
    if (lane == 31) warp_sums[wid] = v;
    __syncthreads();
    if (wid == 0) {
        int w = warp_sums[lane];
#pragma unroll
        for (int o = 1; o < 32; o <<= 1) { int t = __shfl_up_sync(~0u, w, o); if (lane >= o) w += t; }
        warp_sums[lane] = w;
    }
    __syncthreads();
    int excl = v - s + (wid > 0 ? warp_sums[wid - 1] : 0);
    int run = excl;
    for (int i = start; i < end; i++) {
        cursor[i] = run;
        run += counts[i];
        rowptr[i + 1] = run;
    }
    if (tid == 0) rowptr[0] = 0;
}

__global__ void scatter_kernel(const int* __restrict__ src, const int* __restrict__ dst,
                               int* __restrict__ cursor, int* __restrict__ out, int E) {
    int e = blockIdx.x * blockDim.x + threadIdx.x;
    if (e < E) {
        int d = dst[e];
        int pos = atomicAdd(&cursor[d], 1);
        out[pos] = src[e];
    }
}

// ---------------- weight split ----------------
__global__ void split_w_all_kernel(const float* __restrict__ W0, const float* __restrict__ W1,
                                   const float* __restrict__ W2,
                                   __nv_bfloat16* __restrict__ B0, __nv_bfloat16* __restrict__ B1,
                                   __nv_bfloat16* __restrict__ B2) {
    int idx = blockIdx.x * blockDim.x + threadIdx.x;
    const float* W; __nv_bfloat16* Bo; int Ncol;
    if (idx < 16384)      { W = W0; Bo = B0; Ncol = 128; }
    else if (idx < 32768) { W = W1; Bo = B1; Ncol = 128; idx -= 16384; }
    else if (idx < 40960) { W = W2; Bo = B2; Ncol = 64;  idx -= 32768; }
    else return;
    int k = idx / Ncol, n = idx % Ncol;
    float vf = W[idx];
    __nv_bfloat16 hi = __float2bfloat16(vf);
    __nv_bfloat16 lo = __float2bfloat16(vf - __bfloat162float(hi));
    size_t base = (size_t)n * KP;
    Bo[base + k] = hi;
    Bo[base + 128 + k] = hi;
    Bo[base + 256 + k] = lo;
}

// ---------------- mma.sync bf16 GEMM + fused attn coefficients ----------------
// CONVA=1: A is fp32 x [M,128]; convert to split-bf16 hi/lo/hi in smem inline.
// CONVA=0: A is pre-split bf16 [M, KP].
template <int BN, int CONVA, typename OT>
__global__ __launch_bounds__(256, 1) void mma_gemm_kernel(
    const void* __restrict__ Ain, const __nv_bfloat16* __restrict__ B,
    OT* __restrict__ out, const float* __restrict__ asv, const float* __restrict__ adv,
    float* __restrict__ es, float* __restrict__ ed, int M) {
    extern __shared__ __align__(16) __nv_bfloat16 sm[];
    __nv_bfloat16* As = sm;                  // [128][KPAD]
    __nv_bfloat16* Bs = sm + 128 * KPAD;     // [BN][KPAD]
    __shared__ float es_sm[2][128];
    __shared__ float ed_sm[2][128];
    const int tid = threadIdx.x, wid = tid >> 5, lane = tid & 31;
    const int tile = blockIdx.x;

    if constexpr (CONVA) {
        const float* Xg = reinterpret_cast<const float*>(Ain) + (size_t)tile * 128 * CHID;
        const int rows_valid = min(128, M - tile * 128);
        for (int idx = tid; idx < 128 * 64; idx += 256) {
            int row = idx >> 6, c2 = idx & 63;
            float2 v = make_float2(0.f, 0.f);
            if (row < rows_valid)
                v = *reinterpret_cast<const float2*>(Xg + row * CHID + c2 * 2);
            __nv_bfloat16 h0 = __float2bfloat16(v.x);
            __nv_bfloat16 l0 = __float2bfloat16(v.x - __bfloat162float(h0));
            __nv_bfloat16 h1 = __float2bfloat16(v.y);
            __nv_bfloat16 l1 = __float2bfloat16(v.y - __bfloat162float(h1));
            uint32_t hp = (uint32_t)__bfloat16_as_ushort(h0) | ((uint32_t)__bfloat16_as_ushort(h1) << 16);
            uint32_t lp = (uint32_t)__bfloat16_as_ushort(l0) | ((uint32_t)__bfloat16_as_ushort(l1) << 16);
            __nv_bfloat16* rowp = As + row * KPAD + c2 * 2;
            *reinterpret_cast<uint32_t*>(rowp) = hp;
            *reinterpret_cast<uint32_t*>(rowp + 128) = lp;
            *reinterpret_cast<uint32_t*>(rowp + 256) = hp;
        }
    } else {
        const uint4* Ag = reinterpret_cast<const uint4*>(
            reinterpret_cast<const __nv_bfloat16*>(Ain) + (size_t)tile * 128 * KP);
        for (int idx = tid; idx < 128 * 48; idx += 256) {
            int row = idx / 48, ch = idx % 48;
            *reinterpret_cast<uint4*>(As + row * KPAD + ch * 8) = Ag[row * 48 + ch];
        }
    }
    const uint4* Bg = reinterpret_cast<const uint4*>(B);
    for (int idx = tid; idx < BN * 48; idx += 256) {
        int row = idx / 48, ch = idx % 48;
        *reinterpret_cast<uint4*>(Bs + row * KPAD + ch * 8) = Bg[row * 48 + ch];
    }
    __syncthreads();

    constexpr int WN = BN / 2;
    constexpr int NT = WN / 8;
    const int wm = wid & 3, wn = wid >> 2;
    const int m0 = wm * 32, n0 = wn * WN;

    float acc[2][NT][4];
#pragma unroll
    for (int i = 0; i < 2; i++)
#pragma unroll
        for (int j = 0; j < NT; j++)
#pragma unroll
            for (int q = 0; q < 4; q++) acc[i][j][q] = 0.f;

    const uint32_t as_base = smem_u32(As);
    const uint32_t bs_base = smem_u32(Bs);
    const int a_row = m0 + (lane & 15);
    const int a_koff = (lane >> 4) * 8;
    const int b_roff = (lane & 7) + ((lane >> 4) << 3);
    const int b_koff = ((lane >> 3) & 1) * 8;

    uint32_t a_regs[2][2][4];
    uint32_t b_regs[2][NT][2];

#define LOAD_K(ks, buf) do {                                                              \
        const int _k0 = (ks) * 16;                                                        \
        _Pragma("unroll")                                                                 \
        for (int mt = 0; mt < 2; mt++) {                                                  \
            uint32_t addr = as_base + (uint32_t)(((a_row + mt * 16) * KPAD + _k0 + a_koff) * 2); \
            ldm_x4(a_regs[buf][mt], addr);                                                \
        }                                                                                 \
        _Pragma("unroll")                                                                 \
        for (int np = 0; np < NT / 2; np++) {                                             \
            uint32_t addr = bs_base + (uint32_t)(((n0 + np * 16 + b_roff) * KPAD + _k0 + b_koff) * 2); \
            uint32_t r[4];                                                                \
            ldm_x4(r, addr);                                                              \
            b_regs[buf][np * 2][0] = r[0];     b_regs[buf][np * 2][1] = r[1];             \
            b_regs[buf][np * 2 + 1][0] = r[2]; b_regs[buf][np * 2 + 1][1] = r[3];         \
        }                                                                                 \
    } while (0)

    LOAD_K(0, 0);
#pragma unroll
    for (int ks = 0; ks < 24; ks++) {
        const int cur = ks & 1;
        if (ks < 23) LOAD_K(ks + 1, cur ^ 1);
#pragma unroll
        for (int mt = 0; mt < 2; mt++)
#pragma unroll
            for (int nt = 0; nt < NT; nt++)
                mma16816(acc[mt][nt], a_regs[cur][mt], b_regs[cur][nt]);
    }
#undef LOAD_K

    const int g = lane >> 2, q = lane & 3;

    float esp[2][2] = {{0.f, 0.f}, {0.f, 0.f}};
    float edp[2][2] = {{0.f, 0.f}, {0.f, 0.f}};
#pragma unroll
    for (int nt = 0; nt < NT; nt++) {
        int col = n0 + nt * 8 + q * 2;
        float a0 = __ldg(asv + col), a1 = __ldg(asv + col + 1);
        float d0 = __ldg(adv + col), d1 = __ldg(adv + col + 1);
#pragma unroll
        for (int mt = 0; mt < 2; mt++) {
            esp[mt][0] += acc[mt][nt][0] * a0 + acc[mt][nt][1] * a1;
            esp[mt][1] += acc[mt][nt][2] * a0 + acc[mt][nt][3] * a1;
            edp[mt][0] += acc[mt][nt][0] * d0 + acc[mt][nt][1] * d1;
            edp[mt][1] += acc[mt][nt][2] * d0 + acc[mt][nt][3] * d1;
        }
    }
#pragma unroll
    for (int mt = 0; mt < 2; mt++)
#pragma unroll
        for (int r = 0; r < 2; r++) {
            esp[mt][r] += __shfl_xor_sync(~0u, esp[mt][r], 1);
            esp[mt][r] += __shfl_xor_sync(~0u, esp[mt][r], 2);
            edp[mt][r] += __shfl_xor_sync(~0u, edp[mt][r], 1);
            edp[mt][r] += __shfl_xor_sync(~0u, edp[mt][r], 2);
        }
    if (q == 0) {
#pragma unroll
        for (int mt = 0; mt < 2; mt++)
#pragma unroll
            for (int r = 0; r < 2; r++) {
                int row = m0 + mt * 16 + r * 8 + g;
                es_sm[wn][row] = esp[mt][r];
                ed_sm[wn][row] = edp[mt][r];
            }
    }

#pragma unroll
    for (int mt = 0; mt < 2; mt++) {
        int r0 = tile * 128 + m0 + mt * 16 + g;
        int r1 = r0 + 8;
#pragma unroll
        for (int nt = 0; nt < NT; nt++) {
            int col = n0 + nt * 8 + q * 2;
            if (r0 < M)
                *reinterpret_cast<__half2*>(out + (size_t)r0 * BN + col) =
                    __float22half2_rn(make_float2(acc[mt][nt][0], acc[mt][nt][1]));
            if (r1 < M)
                *reinterpret_cast<__half2*>(out + (size_t)r1 * BN + col) =
                    __float22half2_rn(make_float2(acc[mt][nt][2], acc[mt][nt][3]));
        }
    }

    __syncthreads();
    if (tid < 128) {
        int grow = tile * 128 + tid;
        if (grow < M) {
            es[grow] = es_sm[0][tid] + es_sm[1][tid];
            ed[grow] = ed_sm[0][tid] + ed_sm[1][tid];
        }
    }
}

// ---------------- edge-softmax + aggregation: one warp per node ----------------
template <int C, int MODE>
__global__ __launch_bounds__(256) void agg_kernel(
    const __half* __restrict__ h, const float* __restrict__ es,
    const float* __restrict__ ed, const int* __restrict__ rowptr,
    const int* __restrict__ srcs, const float* __restrict__ bias,
    float* __restrict__ out_f32, __nv_bfloat16* __restrict__ out_bf, int N) {
    constexpr int V = C / 32;
    const int gw = (blockIdx.x * blockDim.x + threadIdx.x) >> 5;
    const int lane = threadIdx.x & 31;
    if (gw >= N) return;
    const int d = gw;
    const int start = rowptr[d], end = rowptr[d + 1];
    const float edv = ed[d];

    auto load_row = [&](const __half* hp, float* v) {
        if constexpr (V == 4) {
            uint2 raw = *reinterpret_cast<const uint2*>(hp);
            float2 f0 = __half22float2(*reinterpret_cast<const __half2*>(&raw.x));
            float2 f1 = __half22float2(*reinterpret_cast<const __half2*>(&raw.y));
            v[0] = f0.x; v[1] = f0.y; v[2] = f1.x; v[3] = f1.y;
        } else {
            uint32_t raw = *reinterpret_cast<const uint32_t*>(hp);
            float2 f0 = __half22float2(*reinterpret_cast<const __half2*>(&raw));
            v[0] = f0.x; v[1] = f0.y;
        }
    };

    float wself = __expf(lrelu(es[d] + edv));
    float acc[V];
    {
        float v[V];
        load_row(h + (size_t)d * C + lane * V, v);
#pragma unroll
        for (int i = 0; i < V; i++) acc[i] = wself * v[i];
    }
    float denom = wself;

    int e = start;
    for (; e + 1 < end; e += 2) {
        int s0 = __ldg(srcs + e), s1 = __ldg(srcs + e + 1);
        float w0 = __expf(lrelu(__ldg(es + s0) + edv));
        float w1 = __expf(lrelu(__ldg(es + s1) + edv));
        float v0[V], v1[V];
        load_row(h + (size_t)s0 * C + lane * V, v0);
        load_row(h + (size_t)s1 * C + lane * V, v1);
#pragma unroll
        for (int i = 0; i < V; i++) acc[i] += w0 * v0[i] + w1 * v1[i];
        denom += w0 + w1;
    }
    if (e < end) {
        int s = __ldg(srcs + e);
        float w = __expf(lrelu(__ldg(es + s) + edv));
        float v[V];
        load_row(h + (size_t)s * C + lane * V, v);
#pragma unroll
        for (int i = 0; i < V; i++) acc[i] += w * v[i];
        denom += w;
    }

    const float inv = 1.f / denom;
    if constexpr (MODE == 1) {
        size_t base = (size_t)d * KP;
#pragma unroll
        for (int i = 0; i < V; i++) {
            int ch = lane * V + i;
            float o = fmaxf(acc[i] * inv + __ldg(bias + ch), 0.f);
            __nv_bfloat16 hi = __float2bfloat16(o);
            __nv_bfloat16 lo = __float2bfloat16(o - __bfloat162float(hi));
            out_bf[base + ch] = hi;
            out_bf[base + 128 + ch] = lo;
            out_bf[base + 256 + ch] = hi;
        }
    } else {
#pragma unroll
        for (int i = 0; i < V; i++) {
            int ch = lane * V + i;
            out_f32[(size_t)d * C + ch] = acc[i] * inv + __ldg(bias + ch);
        }
    }
}

// ---------------- launch ----------------
extern "C" void kernel_launch(void* const* d_in, const int* in_sizes, int n_in,
                              void* d_out, int out_size) {
    const float* x   = (const float*)d_in[0];
    const int*   ei  = (const int*)  d_in[1];
    const float* W0  = (const float*)d_in[2];
    const float* as0 = (const float*)d_in[3];
    const float* ad0 = (const float*)d_in[4];
    const float* b0  = (const float*)d_in[5];
    const float* W1  = (const float*)d_in[6];
    const float* as1 = (const float*)d_in[7];
    const float* ad1 = (const float*)d_in[8];
    const float* b1  = (const float*)d_in[9];
    const float* W2  = (const float*)d_in[10];
    const float* as2 = (const float*)d_in[11];
    const float* ad2 = (const float*)d_in[12];
    const float* b2  = (const float*)d_in[13];
    float* out = (float*)d_out;

    const int N = in_sizes[0] / CHID;   // 50000
    const int E = in_sizes[1] / 2;      // 1600000
    const int* srcp = ei;
    const int* dstp = ei + E;

    float *bufA, *es, *ed;
    int *rowptr, *counts, *cursor, *srcs;
    __nv_bfloat16 *Abf, *Bbf0, *Bbf1, *Bbf2;
    cudaGetSymbolAddress((void**)&bufA,   g_bufA);
    cudaGetSymbolAddress((void**)&es,     g_es);
    cudaGetSymbolAddress((void**)&ed,     g_ed);
    cudaGetSymbolAddress((void**)&rowptr, g_rowptr);
    cudaGetSymbolAddress((void**)&counts, g_counts);
    cudaGetSymbolAddress((void**)&cursor, g_cursor);
    cudaGetSymbolAddress((void**)&srcs,   g_srcs);
    cudaGetSymbolAddress((void**)&Abf,    g_Abf);
    cudaGetSymbolAddress((void**)&Bbf0,   g_Bbf0);
    cudaGetSymbolAddress((void**)&Bbf1,   g_Bbf1);
    cudaGetSymbolAddress((void**)&Bbf2,   g_Bbf2);
    __half* bufH = reinterpret_cast<__half*>(bufA);

    const int smem128 = (128 + 128) * KPAD * 2;   // 200704
    const int smem64  = (128 + 64)  * KPAD * 2;   // 150528

    static cudaStream_t s2 = nullptr;
    static cudaEvent_t ev_fork = nullptr, ev_join = nullptr;
    if (!s2) {   // first (uncaptured correctness) call only
        cudaStreamCreateWithFlags(&s2, cudaStreamNonBlocking);
        cudaEventCreateWithFlags(&ev_fork, cudaEventDisableTiming);
        cudaEventCreateWithFlags(&ev_join, cudaEventDisableTiming);
        cudaFuncSetAttribute((const void*)mma_gemm_kernel<128, 1, __half>,
                             cudaFuncAttributeMaxDynamicSharedMemorySize, smem128);
        cudaFuncSetAttribute((const void*)mma_gemm_kernel<128, 0, __half>,
                             cudaFuncAttributeMaxDynamicSharedMemorySize, smem128);
        cudaFuncSetAttribute((const void*)mma_gemm_kernel<64, 0, __half>,
                             cudaFuncAttributeMaxDynamicSharedMemorySize, smem64);
    }

    const int eb = (E + 255) / 256;
    const int tiles = (N + 127) / 128;       // 391
    const int aggb = (N * 32 + 255) / 256;   // warp-per-node

    // ---- fork: CSR build on s2, overlapped with split_w + gemm0 ----
    cudaEventRecord(ev_fork, 0);
    cudaStreamWaitEvent(s2, ev_fork, 0);
    cudaMemsetAsync(counts, 0, N * sizeof(int), s2);
    count_kernel<<<eb, 256, 0, s2>>>(dstp, counts, E);
    scan_kernel<<<1, 1024, 0, s2>>>(counts, rowptr, cursor, N);
    scatter_kernel<<<eb, 256, 0, s2>>>(srcp, dstp, cursor, srcs, E);
    cudaEventRecord(ev_join, s2);

    // ---- main stream: layer 0 GEMM reads fp32 x directly ----
    split_w_all_kernel<<<(40960 + 255) / 256, 256>>>(W0, W1, W2, Bbf0, Bbf1, Bbf2);
    mma_gemm_kernel<128, 1, __half><<<tiles, 256, smem128>>>(x, Bbf0, bufH, as0, ad0, es, ed, N);

    cudaStreamWaitEvent(0, ev_join, 0);   // join: agg needs CSR

    agg_kernel<128, 1><<<aggb, 256>>>(bufH, es, ed, rowptr, srcs, b0, nullptr, Abf, N);

    mma_gemm_kernel<128, 0, __half><<<tiles, 256, smem128>>>(Abf, Bbf1, bufH, as1, ad1, es, ed, N);
    agg_kernel<128, 1><<<aggb, 256>>>(bufH, es, ed, rowptr, srcs, b1, nullptr, Abf, N);

    mma_gemm_kernel<64, 0, __half><<<tiles, 256, smem64>>>(Abf, Bbf2, bufH, as2, ad2, es, ed, N);
    agg_kernel<64, 0><<<aggb, 256>>>(bufH, es, ed, rowptr, srcs, b2, out, nullptr, N);
}

// round 17
// speedup vs baseline: 1.8990x; 1.0566x over previous
#include <cuda_runtime.h>
#include <cuda_bf16.h>
#include <cuda_fp16.h>
#include <cstdint>

#define NNODES 50000
#define NPAD   50048          // 391 * 128
#define NEDGES 1600000
#define CHID   128
#define KP     384            // split-bf16 K' = 3 * 128
#define BK     96             // k-chunk size
#define PITCH  104            // smem chunk row pitch in bf16 (208B rows, conflict-free ldmatrix)
#define CHUNKS 4              // KP / BK
#define KSTEPS 6              // BK / 16

// ---------------- scratch (no allocations allowed) ----------------
__device__ float g_bufA[NNODES * CHID];   // viewed as __half h buffer
__device__ float g_es[NNODES];
__device__ float g_ed[NNODES];
__device__ int   g_rowptr[NNODES + 1];
__device__ int   g_counts[NNODES];
__device__ int   g_cursor[NNODES];
__device__ int   g_srcs[NEDGES];
__device__ __nv_bfloat16 g_Abf[(size_t)NPAD * KP];   // padded rows stay zero
__device__ __nv_bfloat16 g_Bbf0[(size_t)CHID * KP];
__device__ __nv_bfloat16 g_Bbf1[(size_t)CHID * KP];
__device__ __nv_bfloat16 g_Bbf2[(size_t)64 * KP];

__device__ __forceinline__ float lrelu(float x) { return x > 0.f ? x : 0.2f * x; }

__device__ __forceinline__ uint32_t smem_u32(const void* p) {
    uint32_t a;
    asm("{ .reg .u64 t; cvta.to.shared.u64 t, %1; cvt.u32.u64 %0, t; }" : "=r"(a) : "l"(p));
    return a;
}
__device__ __forceinline__ void ldm_x4(uint32_t* r, uint32_t addr) {
    asm volatile("ldmatrix.sync.aligned.m8n8.x4.shared.b16 {%0,%1,%2,%3}, [%4];"
                 : "=r"(r[0]), "=r"(r[1]), "=r"(r[2]), "=r"(r[3]) : "r"(addr));
}
__device__ __forceinline__ void mma16816(float* c, const uint32_t* a, const uint32_t* b) {
    asm volatile("mma.sync.aligned.m16n8k16.row.col.f32.bf16.bf16.f32 "
                 "{%0,%1,%2,%3}, {%4,%5,%6,%7}, {%8,%9}, {%0,%1,%2,%3};"
                 : "+f"(c[0]), "+f"(c[1]), "+f"(c[2]), "+f"(c[3])
                 : "r"(a[0]), "r"(a[1]), "r"(a[2]), "r"(a[3]), "r"(b[0]), "r"(b[1]));
}
#define CP_ASYNC16(s, g) \
    asm volatile("cp.async.cg.shared.global [%0], [%1], 16;" :: "r"(s), "l"(g) : "memory")
#define CP_COMMIT() asm volatile("cp.async.commit_group;" ::: "memory")
#define CP_WAIT1()  asm volatile("cp.async.wait_group 1;" ::: "memory")
#define CP_WAIT0()  asm volatile("cp.async.wait_group 0;" ::: "memory")

// ---------------- CSR build ----------------
__global__ void count_kernel(const int* __restrict__ dst, int* __restrict__ counts, int E) {
    int e = blockIdx.x * blockDim.x + threadIdx.x;
    if (e < E) atomicAdd(&counts[dst[e]], 1);
}

__global__ void scan_kernel(const int* __restrict__ counts, int* __restrict__ rowptr,
                            int* __restrict__ cursor, int n) {
    __shared__ int warp_sums[32];
    int tid = threadIdx.x;
    int CH = (n + 1023) >> 10;
    int start = tid * CH;
    int end = min(start + CH, n);
    int s = 0;
    for (int i = start; i < end; i++) s += counts[i];
    int lane = tid & 31, wid = tid >> 5;
    int v = s;
#pragma unroll
    for (int o = 1; o < 32; o <<= 1) { int t = __shfl_up_sync(~0u, v, o); if (lane >= o) v += t; }
    if (lane == 31) warp_sums[wid] = v;
    __syncthreads();
    if (wid == 0) {
        int w = warp_sums[lane];
#pragma unroll
        for (int o = 1; o < 32; o <<= 1) { int t = __shfl_up_sync(~0u, w, o); if (lane >= o) w += t; }
        warp_sums[lane] = w;
    }
    __syncthreads();
    int excl = v - s + (wid > 0 ? warp_sums[wid - 1] : 0);
    int run = excl;
    for (int i = start; i < end; i++) {
        cursor[i] = run;
        run += counts[i];
        rowptr[i + 1] = run;
    }
    if (tid == 0) rowptr[0] = 0;
}

__global__ void scatter_kernel(const int* __restrict__ src, const int* __restrict__ dst,
                               int* __restrict__ cursor, int* __restrict__ out, int E) {
    int e = blockIdx.x * blockDim.x + threadIdx.x;
    if (e < E) {
        int d = dst[e];
        int pos = atomicAdd(&cursor[d], 1);
        out[pos] = src[e];
    }
}

// ---------------- weight split ----------------
__global__ void split_w_all_kernel(const float* __restrict__ W0, const float* __restrict__ W1,
                                   const float* __restrict__ W2,
                                   __nv_bfloat16* __restrict__ B0, __nv_bfloat16* __restrict__ B1,
                                   __nv_bfloat16* __restrict__ B2) {
    int idx = blockIdx.x * blockDim.x + threadIdx.x;
    const float* W; __nv_bfloat16* Bo; int Ncol;
    if (idx < 16384)      { W = W0; Bo = B0; Ncol = 128; }
    else if (idx < 32768) { W = W1; Bo = B1; Ncol = 128; idx -= 16384; }
    else if (idx < 40960) { W = W2; Bo = B2; Ncol = 64;  idx -= 32768; }
    else return;
    int k = idx / Ncol, n = idx % Ncol;
    float vf = W[idx];
    __nv_bfloat16 hi = __float2bfloat16(vf);
    __nv_bfloat16 lo = __float2bfloat16(vf - __bfloat162float(hi));
    size_t base = (size_t)n * KP;
    Bo[base + k] = hi;
    Bo[base + 128 + k] = hi;
    Bo[base + 256 + k] = lo;
}

// ---------------- chunked cp.async pipelined bf16 GEMM + fused attn coefficients ----------------
// CONVA=1: A is fp32 x [M,128]; chunk conversion to split-bf16 inline (scalar LDG+STS).
// CONVA=0: A is pre-split bf16 [M, KP]; chunk loaded via cp.async.
// smem = 2 A-chunk bufs + 2 B-chunk bufs = (2*128 + 2*BN) * PITCH * 2 bytes -> 2 CTAs/SM.
template <int BN, int CONVA>
__global__ __launch_bounds__(256, 2) void mma_gemm_kernel(
    const void* __restrict__ Ain, const __nv_bfloat16* __restrict__ B,
    __half* __restrict__ out, const float* __restrict__ asv, const float* __restrict__ adv,
    float* __restrict__ es, float* __restrict__ ed, int M) {
    extern __shared__ __align__(16) __nv_bfloat16 sm[];
    constexpr int ASZ = 128 * PITCH;          // elems per A buf
    constexpr int BSZ = BN * PITCH;
    __shared__ float es_sm[2][128];
    __shared__ float ed_sm[2][128];
    const int tid = threadIdx.x, wid = tid >> 5, lane = tid & 31;
    const int tile = blockIdx.x;
    const uint32_t smbase = smem_u32(sm);

    const int rows_valid = CONVA ? min(128, M - tile * 128) : 128;

    // ---- chunk load stages ----
    auto load_A = [&](int c, int b) {
        if constexpr (CONVA) {
            const float* Xg = reinterpret_cast<const float*>(Ain) + (size_t)tile * 128 * CHID;
            __nv_bfloat16* Ab = sm + b * ASZ;
            const int kbase = c * BK;
            for (int idx = tid; idx < 128 * BK; idx += 256) {
                int row = idx / BK, j = idx % BK;
                int kk = kbase + j;
                int cx = kk & 127;
                float v = (row < rows_valid) ? __ldg(Xg + row * CHID + cx) : 0.f;
                __nv_bfloat16 hv = __float2bfloat16(v);
                __nv_bfloat16 ov = ((kk >> 7) == 1)
                    ? __float2bfloat16(v - __bfloat162float(hv)) : hv;
                Ab[row * PITCH + j] = ov;
            }
        } else {
            const char* Ag = reinterpret_cast<const char*>(
                reinterpret_cast<const __nv_bfloat16*>(Ain) + (size_t)tile * 128 * KP + c * BK);
            uint32_t sb = smbase + b * ASZ * 2;
#pragma unroll
            for (int t = 0; t < 6; t++) {
                int idx = tid + t * 256;
                int row = idx / 12, ch = idx % 12;
                CP_ASYNC16(sb + row * (PITCH * 2) + ch * 16, Ag + (size_t)row * (KP * 2) + ch * 16);
            }
        }
    };
    auto load_B = [&](int c, int b) {
        const char* Bg = reinterpret_cast<const char*>(B + c * BK);
        uint32_t sb = smbase + (2 * ASZ + b * BSZ) * 2;
#pragma unroll
        for (int t = 0; t < (BN * 12) / 256; t++) {
            int idx = tid + t * 256;
            int row = idx / 12, ch = idx % 12;
            CP_ASYNC16(sb + row * (PITCH * 2) + ch * 16, Bg + (size_t)row * (KP * 2) + ch * 16);
        }
    };

    constexpr int WN = BN / 2;
    constexpr int NT = WN / 8;
    const int wm = wid & 3, wn = wid >> 2;
    const int m0 = wm * 32, n0 = wn * WN;

    float acc[2][NT][4];
#pragma unroll
    for (int i = 0; i < 2; i++)
#pragma unroll
        for (int j = 0; j < NT; j++)
#pragma unroll
            for (int q = 0; q < 4; q++) acc[i][j][q] = 0.f;

    const int a_row = m0 + (lane & 15);
    const int a_koff = (lane >> 4) * 8;
    const int b_roff = (lane & 7) + ((lane >> 4) << 3);
    const int b_koff = ((lane >> 3) & 1) * 8;

    // ---- pipeline: prologue ----
    load_A(0, 0);
    load_B(0, 0);
    CP_COMMIT();

#pragma unroll
    for (int c = 0; c < CHUNKS; c++) {
        const int cur = c & 1;
        if (c + 1 < CHUNKS) {
            load_A(c + 1, cur ^ 1);
            load_B(c + 1, cur ^ 1);
            CP_COMMIT();
            CP_WAIT1();
        } else {
            CP_WAIT0();
        }
        __syncthreads();

        const uint32_t as_base = smbase + cur * ASZ * 2;
        const uint32_t bs_base = smbase + (2 * ASZ + cur * BSZ) * 2;
#pragma unroll
        for (int ks = 0; ks < KSTEPS; ks++) {
            const int k0 = ks * 16;
            uint32_t a_regs[2][4];
#pragma unroll
            for (int mt = 0; mt < 2; mt++)
                ldm_x4(a_regs[mt], as_base + (uint32_t)(((a_row + mt * 16) * PITCH + k0 + a_koff) * 2));
            uint32_t b_regs[NT][2];
#pragma unroll
            for (int np = 0; np < NT / 2; np++) {
                uint32_t r[4];
                ldm_x4(r, bs_base + (uint32_t)(((n0 + np * 16 + b_roff) * PITCH + k0 + b_koff) * 2));
                b_regs[np * 2][0] = r[0];     b_regs[np * 2][1] = r[1];
                b_regs[np * 2 + 1][0] = r[2]; b_regs[np * 2 + 1][1] = r[3];
            }
#pragma unroll
            for (int mt = 0; mt < 2; mt++)
#pragma unroll
                for (int nt = 0; nt < NT; nt++)
                    mma16816(acc[mt][nt], a_regs[mt], b_regs[nt]);
        }
        __syncthreads();
    }

    const int g = lane >> 2, q = lane & 3;

    // fused attn coefficients
    float esp[2][2] = {{0.f, 0.f}, {0.f, 0.f}};
    float edp[2][2] = {{0.f, 0.f}, {0.f, 0.f}};
#pragma unroll
    for (int nt = 0; nt < NT; nt++) {
        int col = n0 + nt * 8 + q * 2;
        float a0 = __ldg(asv + col), a1 = __ldg(asv + col + 1);
        float d0 = __ldg(adv + col), d1 = __ldg(adv + col + 1);
#pragma unroll
        for (int mt = 0; mt < 2; mt++) {
            esp[mt][0] += acc[mt][nt][0] * a0 + acc[mt][nt][1] * a1;
            esp[mt][1] += acc[mt][nt][2] * a0 + acc[mt][nt][3] * a1;
            edp[mt][0] += acc[mt][nt][0] * d0 + acc[mt][nt][1] * d1;
            edp[mt][1] += acc[mt][nt][2] * d0 + acc[mt][nt][3] * d1;
        }
    }
#pragma unroll
    for (int mt = 0; mt < 2; mt++)
#pragma unroll
        for (int r = 0; r < 2; r++) {
            esp[mt][r] += __shfl_xor_sync(~0u, esp[mt][r], 1);
            esp[mt][r] += __shfl_xor_sync(~0u, esp[mt][r], 2);
            edp[mt][r] += __shfl_xor_sync(~0u, edp[mt][r], 1);
            edp[mt][r] += __shfl_xor_sync(~0u, edp[mt][r], 2);
        }
    if (q == 0) {
#pragma unroll
        for (int mt = 0; mt < 2; mt++)
#pragma unroll
            for (int r = 0; r < 2; r++) {
                int row = m0 + mt * 16 + r * 8 + g;
                es_sm[wn][row] = esp[mt][r];
                ed_sm[wn][row] = edp[mt][r];
            }
    }

    // h store (fp16)
#pragma unroll
    for (int mt = 0; mt < 2; mt++) {
        int r0 = tile * 128 + m0 + mt * 16 + g;
        int r1 = r0 + 8;
#pragma unroll
        for (int nt = 0; nt < NT; nt++) {
            int col = n0 + nt * 8 + q * 2;
            if (r0 < M)
                *reinterpret_cast<__half2*>(out + (size_t)r0 * BN + col) =
                    __float22half2_rn(make_float2(acc[mt][nt][0], acc[mt][nt][1]));
            if (r1 < M)
                *reinterpret_cast<__half2*>(out + (size_t)r1 * BN + col) =
                    __float22half2_rn(make_float2(acc[mt][nt][2], acc[mt][nt][3]));
        }
    }

    __syncthreads();
    if (tid < 128) {
        int grow = tile * 128 + tid;
        if (grow < M) {
            if constexpr (BN == 128) {
                es[grow] = es_sm[0][tid] + es_sm[1][tid];
                ed[grow] = ed_sm[0][tid] + ed_sm[1][tid];
            } else {
                es[grow] = es_sm[0][tid] + es_sm[1][tid];
                ed[grow] = ed_sm[0][tid] + ed_sm[1][tid];
            }
        }
    }
}

// ---------------- edge-softmax + aggregation: one warp per node ----------------
template <int C, int MODE>
__global__ __launch_bounds__(256) void agg_kernel(
    const __half* __restrict__ h, const float* __restrict__ es,
    const float* __restrict__ ed, const int* __restrict__ rowptr,
    const int* __restrict__ srcs, const float* __restrict__ bias,
    float* __restrict__ out_f32, __nv_bfloat16* __restrict__ out_bf, int N) {
    constexpr int V = C / 32;
    const int gw = (blockIdx.x * blockDim.x + threadIdx.x) >> 5;
    const int lane = threadIdx.x & 31;
    if (gw >= N) return;
    const int d = gw;
    const int start = rowptr[d], end = rowptr[d + 1];
    const float edv = ed[d];

    auto load_row = [&](const __half* hp, float* v) {
        if constexpr (V == 4) {
            uint2 raw = *reinterpret_cast<const uint2*>(hp);
            float2 f0 = __half22float2(*reinterpret_cast<const __half2*>(&raw.x));
            float2 f1 = __half22float2(*reinterpret_cast<const __half2*>(&raw.y));
            v[0] = f0.x; v[1] = f0.y; v[2] = f1.x; v[3] = f1.y;
        } else {
            uint32_t raw = *reinterpret_cast<const uint32_t*>(hp);
            float2 f0 = __half22float2(*reinterpret_cast<const __half2*>(&raw));
            v[0] = f0.x; v[1] = f0.y;
        }
    };

    float wself = __expf(lrelu(es[d] + edv));
    float acc[V];
    {
        float v[V];
        load_row(h + (size_t)d * C + lane * V, v);
#pragma unroll
        for (int i = 0; i < V; i++) acc[i] = wself * v[i];
    }
    float denom = wself;

    int e = start;
    for (; e + 1 < end; e += 2) {
        int s0 = __ldg(srcs + e), s1 = __ldg(srcs + e + 1);
        float w0 = __expf(lrelu(__ldg(es + s0) + edv));
        float w1 = __expf(lrelu(__ldg(es + s1) + edv));
        float v0[V], v1[V];
        load_row(h + (size_t)s0 * C + lane * V, v0);
        load_row(h + (size_t)s1 * C + lane * V, v1);
#pragma unroll
        for (int i = 0; i < V; i++) acc[i] += w0 * v0[i] + w1 * v1[i];
        denom += w0 + w1;
    }
    if (e < end) {
        int s = __ldg(srcs + e);
        float w = __expf(lrelu(__ldg(es + s) + edv));
        float v[V];
        load_row(h + (size_t)s * C + lane * V, v);
#pragma unroll
        for (int i = 0; i < V; i++) acc[i] += w * v[i];
        denom += w;
    }

    const float inv = 1.f / denom;
    if constexpr (MODE == 1) {
        size_t base = (size_t)d * KP;
#pragma unroll
        for (int i = 0; i < V; i++) {
            int ch = lane * V + i;
            float o = fmaxf(acc[i] * inv + __ldg(bias + ch), 0.f);
            __nv_bfloat16 hi = __float2bfloat16(o);
            __nv_bfloat16 lo = __float2bfloat16(o - __bfloat162float(hi));
            out_bf[base + ch] = hi;
            out_bf[base + 128 + ch] = lo;
            out_bf[base + 256 + ch] = hi;
        }
    } else {
#pragma unroll
        for (int i = 0; i < V; i++) {
            int ch = lane * V + i;
            out_f32[(size_t)d * C + ch] = acc[i] * inv + __ldg(bias + ch);
        }
    }
}

// ---------------- launch ----------------
extern "C" void kernel_launch(void* const* d_in, const int* in_sizes, int n_in,
                              void* d_out, int out_size) {
    const float* x   = (const float*)d_in[0];
    const int*   ei  = (const int*)  d_in[1];
    const float* W0  = (const float*)d_in[2];
    const float* as0 = (const float*)d_in[3];
    const float* ad0 = (const float*)d_in[4];
    const float* b0  = (const float*)d_in[5];
    const float* W1  = (const float*)d_in[6];
    const float* as1 = (const float*)d_in[7];
    const float* ad1 = (const float*)d_in[8];
    const float* b1  = (const float*)d_in[9];
    const float* W2  = (const float*)d_in[10];
    const float* as2 = (const float*)d_in[11];
    const float* ad2 = (const float*)d_in[12];
    const float* b2  = (const float*)d_in[13];
    float* out = (float*)d_out;

    const int N = in_sizes[0] / CHID;   // 50000
    const int E = in_sizes[1] / 2;      // 1600000
    const int* srcp = ei;
    const int* dstp = ei + E;

    float *bufA, *es, *ed;
    int *rowptr, *counts, *cursor, *srcs;
    __nv_bfloat16 *Abf, *Bbf0, *Bbf1, *Bbf2;
    cudaGetSymbolAddress((void**)&bufA,   g_bufA);
    cudaGetSymbolAddress((void**)&es,     g_es);
    cudaGetSymbolAddress((void**)&ed,     g_ed);
    cudaGetSymbolAddress((void**)&rowptr, g_rowptr);
    cudaGetSymbolAddress((void**)&counts, g_counts);
    cudaGetSymbolAddress((void**)&cursor, g_cursor);
    cudaGetSymbolAddress((void**)&srcs,   g_srcs);
    cudaGetSymbolAddress((void**)&Abf,    g_Abf);
    cudaGetSymbolAddress((void**)&Bbf0,   g_Bbf0);
    cudaGetSymbolAddress((void**)&Bbf1,   g_Bbf1);
    cudaGetSymbolAddress((void**)&Bbf2,   g_Bbf2);
    __half* bufH = reinterpret_cast<__half*>(bufA);

    const int smem128 = (2 * 128 + 2 * 128) * PITCH * 2;   // 106496
    const int smem64  = (2 * 128 + 2 * 64)  * PITCH * 2;   // 79872

    static cudaStream_t s2 = nullptr;
    static cudaEvent_t ev_fork = nullptr, ev_join = nullptr;
    if (!s2) {   // first (uncaptured correctness) call only
        cudaStreamCreateWithFlags(&s2, cudaStreamNonBlocking);
        cudaEventCreateWithFlags(&ev_fork, cudaEventDisableTiming);
        cudaEventCreateWithFlags(&ev_join, cudaEventDisableTiming);
        cudaFuncSetAttribute((const void*)mma_gemm_kernel<128, 1>,
                             cudaFuncAttributeMaxDynamicSharedMemorySize, smem128);
        cudaFuncSetAttribute((const void*)mma_gemm_kernel<128, 0>,
                             cudaFuncAttributeMaxDynamicSharedMemorySize, smem128);
        cudaFuncSetAttribute((const void*)mma_gemm_kernel<64, 0>,
                             cudaFuncAttributeMaxDynamicSharedMemorySize, smem64);
    }

    const int eb = (E + 255) / 256;
    const int tiles = (N + 127) / 128;       // 391
    const int aggb = (N * 32 + 255) / 256;   // warp-per-node

    // ---- fork: CSR build on s2, overlapped with split_w + gemm0 ----
    cudaEventRecord(ev_fork, 0);
    cudaStreamWaitEvent(s2, ev_fork, 0);
    cudaMemsetAsync(counts, 0, N * sizeof(int), s2);
    count_kernel<<<eb, 256, 0, s2>>>(dstp, counts, E);
    scan_kernel<<<1, 1024, 0, s2>>>(counts, rowptr, cursor, N);
    scatter_kernel<<<eb, 256, 0, s2>>>(srcp, dstp, cursor, srcs, E);
    cudaEventRecord(ev_join, s2);

    // ---- main stream ----
    split_w_all_kernel<<<(40960 + 255) / 256, 256>>>(W0, W1, W2, Bbf0, Bbf1, Bbf2);
    mma_gemm_kernel<128, 1><<<tiles, 256, smem128>>>(x, Bbf0, bufH, as0, ad0, es, ed, N);

    cudaStreamWaitEvent(0, ev_join, 0);   // join: agg needs CSR

    agg_kernel<128, 1><<<aggb, 256>>>(bufH, es, ed, rowptr, srcs, b0, nullptr, Abf, N);

    mma_gemm_kernel<128, 0><<<tiles, 256, smem128>>>(Abf, Bbf1, bufH, as1, ad1, es, ed, N);
    agg_kernel<128, 1><<<aggb, 256>>>(bufH, es, ed, rowptr, srcs, b1, nullptr, Abf, N);

    mma_gemm_kernel<64, 0><<<tiles, 256, smem64>>>(Abf, Bbf2, bufH, as2, ad2, es, ed, N);
    agg_kernel<64, 0><<<aggb, 256>>>(bufH, es, ed, rowptr, srcs, b2, out, nullptr, N);
}